// round 1
// baseline (speedup 1.0000x reference)
#include <cuda_runtime.h>
#include <math_constants.h>

// ---------------------------------------------------------------------------
// HigherOrderAttention (2-simplicial attention) — fp32 baseline
//   tokens[2,192,512] -> qkv GEMM -> rmsnorm(q,k1,k2,v1,v2) ->
//   flash-style online softmax over (j,k) with per-k small GEMMs ->
//   combine split-K partials -> output GEMM.
// ---------------------------------------------------------------------------

#define TOK_B   2
#define SEQ     192
#define DIMM    512
#define HEADS   8
#define DH      64
#define BHD     (TOK_B * HEADS)        // 16
#define QKV_C   2560                   // 512 + 1024 + 1024
#define ROWS    (TOK_B * SEQ)          // 384
#define KSPLIT  2
#define KRANGE  (SEQ / KSPLIT)         // 96
#define TI      16                     // i-tile rows per block
#define NTILES  (SEQ / TI)             // 12

// Scratch (device globals; no runtime allocation allowed)
__device__ float g_qkv[ROWS * QKV_C];
__device__ float g_q [BHD * SEQ * DH];
__device__ float g_k1[BHD * SEQ * DH];
__device__ float g_k2[BHD * SEQ * DH];
__device__ float g_v1[BHD * SEQ * DH];
__device__ float g_v2[BHD * SEQ * DH];
__device__ float g_pacc[KSPLIT * BHD * SEQ * DH];
__device__ float g_pm  [KSPLIT * BHD * SEQ];
__device__ float g_pl  [KSPLIT * BHD * SEQ];
__device__ float g_attn[ROWS * DIMM];

// ---------------------------------------------------------------------------
// Tiled NT GEMM: C[M,Nc] = A[M,K] * B[Nc,K]^T  (both K-contiguous, row-major)
// 64x64 tile per block, 256 threads, 4x4 per thread, TK=32.
// ---------------------------------------------------------------------------
__global__ __launch_bounds__(256) void gemm_nt64(
    const float* __restrict__ A, const float* __restrict__ Bm,
    float* __restrict__ C, int M, int Nc, int K)
{
    __shared__ float As[32][68];   // As[kk][row] (transposed for float4 reads)
    __shared__ float Bs[32][68];

    const int t  = threadIdx.x;
    const int ti = t >> 4;         // 0..15
    const int tj = t & 15;         // 0..15
    const int m0 = blockIdx.y * 64;
    const int n0 = blockIdx.x * 64;

    float c[4][4];
#pragma unroll
    for (int a = 0; a < 4; ++a)
#pragma unroll
        for (int b = 0; b < 4; ++b) c[a][b] = 0.f;

    for (int k0 = 0; k0 < K; k0 += 32) {
#pragma unroll
        for (int r = 0; r < 8; ++r) {
            int e   = t + 256 * r;
            int row = e >> 5;      // 0..63
            int kk  = e & 31;
            As[kk][row] = A [(m0 + row) * K + k0 + kk];
            Bs[kk][row] = Bm[(n0 + row) * K + k0 + kk];
        }
        __syncthreads();
#pragma unroll
        for (int kk = 0; kk < 32; ++kk) {
            float4 a4 = *(const float4*)&As[kk][ti * 4];
            float4 b4 = *(const float4*)&Bs[kk][tj * 4];
            const float av[4] = {a4.x, a4.y, a4.z, a4.w};
            const float bv[4] = {b4.x, b4.y, b4.z, b4.w};
#pragma unroll
            for (int ii = 0; ii < 4; ++ii)
#pragma unroll
                for (int jj = 0; jj < 4; ++jj)
                    c[ii][jj] = fmaf(av[ii], bv[jj], c[ii][jj]);
        }
        __syncthreads();
    }
#pragma unroll
    for (int ii = 0; ii < 4; ++ii)
#pragma unroll
        for (int jj = 0; jj < 4; ++jj)
            C[(m0 + ti * 4 + ii) * Nc + n0 + tj * 4 + jj] = c[ii][jj];
}

// ---------------------------------------------------------------------------
// RMSNorm + head split/scatter. One warp per (b,n,h); 5 vectors of 64.
// ---------------------------------------------------------------------------
__device__ __forceinline__ void rms_one(const float* __restrict__ x,
                                        const float* __restrict__ w,
                                        float* __restrict__ y, int lane)
{
    float x0 = x[lane];
    float x1 = x[lane + 32];
    float ss = x0 * x0 + x1 * x1;
#pragma unroll
    for (int o = 16; o >= 1; o >>= 1)
        ss += __shfl_xor_sync(0xffffffffu, ss, o);
    float inv = rsqrtf(ss * (1.0f / 64.0f) + 1.1920929e-07f);
    y[lane]      = x0 * inv * w[lane];
    y[lane + 32] = x1 * inv * w[lane + 32];
}

__global__ __launch_bounds__(32) void rmsnorm_kernel(
    const float* __restrict__ qkv,
    const float* __restrict__ qw,  const float* __restrict__ k1w,
    const float* __restrict__ k2w, const float* __restrict__ v1w,
    const float* __restrict__ v2w,
    float* __restrict__ gq,  float* __restrict__ gk1, float* __restrict__ gk2,
    float* __restrict__ gv1, float* __restrict__ gv2)
{
    const int id   = blockIdx.x;        // (b*SEQ + n)*HEADS + h
    const int h    = id & 7;
    const int bn   = id >> 3;           // b*SEQ + n
    const int b    = bn / SEQ;
    const int n    = bn % SEQ;
    const int lane = threadIdx.x;

    const float* base = qkv + bn * QKV_C;
    const int dst = ((b * HEADS + h) * SEQ + n) * DH;

    rms_one(base + h * DH,                   qw,  gq  + dst, lane);
    rms_one(base + 512  + h * 128,           k1w, gk1 + dst, lane);
    rms_one(base + 512  + h * 128 + DH,      k2w, gk2 + dst, lane);
    rms_one(base + 1536 + h * 128,           v1w, gv1 + dst, lane);
    rms_one(base + 1536 + h * 128 + DH,      v2w, gv2 + dst, lane);
}

// ---------------------------------------------------------------------------
// Attention with online softmax over the flattened (j,k) axis.
// Block = (split, i-tile, bh). 256 threads: thread -> (i = t/16, g = t%16),
// owns d = 4g..4g+3 and j = {g*4+c + 64*jj}.
// smem: k1T[64][200] (d-major, transposed), v1[192][64], q[16][64],
//       qk2[16][64], p[16][192].
// ---------------------------------------------------------------------------
#define SM_K1T  (64 * 200)
#define SM_V1   (SEQ * DH)
#define SM_Q    (TI * DH)
#define SM_QK2  (TI * DH)
#define SM_P    (TI * SEQ)
#define SMEM_FLOATS (SM_K1T + SM_V1 + SM_Q + SM_QK2 + SM_P)
#define SMEM_BYTES  (SMEM_FLOATS * 4)

__global__ __launch_bounds__(256, 1) void attn_kernel(
    const float* __restrict__ gq,  const float* __restrict__ gk1,
    const float* __restrict__ gk2, const float* __restrict__ gv1,
    const float* __restrict__ gv2,
    float* __restrict__ pacc, float* __restrict__ pm, float* __restrict__ pl)
{
    extern __shared__ __align__(16) float sm[];
    float* k1T = sm;                       // [64][200]
    float* v1s = k1T + SM_K1T;             // [192][64]
    float* qs  = v1s + SM_V1;              // [16][64]
    float* qk2 = qs  + SM_Q;               // [16][64]
    float* ps  = qk2 + SM_QK2;             // [16][192]

    const int split = blockIdx.x;
    const int i0    = blockIdx.y * TI;
    const int bh    = blockIdx.z;
    const int t     = threadIdx.x;

    const float* k1b = gk1 + bh * SEQ * DH;
    const float* v1b = gv1 + bh * SEQ * DH;
    const float* k2b = gk2 + bh * SEQ * DH;
    const float* v2b = gv2 + bh * SEQ * DH;
    const float* qb  = gq  + (bh * SEQ + i0) * DH;

    // Load tiles: k1 transposed to [d][j], v1 as [j][d], q tile [i][d]
    for (int e = t; e < SEQ * DH; e += 256) {
        int j = e >> 6, d = e & 63;
        k1T[d * 200 + j] = k1b[e];
        v1s[e]           = v1b[e];
    }
    for (int e = t; e < TI * DH; e += 256) qs[e] = qb[e];

    const int i = t >> 4;
    const int g = t & 15;

    float m = -CUDART_INF_F;
    float l = 0.f;
    float4 acc = make_float4(0.f, 0.f, 0.f, 0.f);

    const int kbeg = split * KRANGE;
    const int kend = kbeg + KRANGE;

    for (int k = kbeg; k < kend; ++k) {
        __syncthreads();   // also covers the initial tile loads
        // qk2 = q * k2[k] * scale (scale folded in here)
#pragma unroll
        for (int c = 0; c < 4; ++c) {
            int e = t * 4 + c;
            int d = e & 63;
            qk2[e] = qs[e] * k2b[k * DH + d] * 0.125f;
        }
        __syncthreads();

        // ---- S[i][j] = sum_d qk2[i][d] * k1[j][d] -------------------------
        float4 s0 = make_float4(0.f,0.f,0.f,0.f);
        float4 s1 = make_float4(0.f,0.f,0.f,0.f);
        float4 s2 = make_float4(0.f,0.f,0.f,0.f);
        const float* qi = qk2 + i * 64;
#pragma unroll 4
        for (int d = 0; d < 64; ++d) {
            float qd = qi[d];
            const float* kr = k1T + d * 200 + g * 4;
            float4 b0 = *(const float4*)(kr);
            float4 b1 = *(const float4*)(kr + 64);
            float4 b2 = *(const float4*)(kr + 128);
            s0.x = fmaf(qd, b0.x, s0.x); s0.y = fmaf(qd, b0.y, s0.y);
            s0.z = fmaf(qd, b0.z, s0.z); s0.w = fmaf(qd, b0.w, s0.w);
            s1.x = fmaf(qd, b1.x, s1.x); s1.y = fmaf(qd, b1.y, s1.y);
            s1.z = fmaf(qd, b1.z, s1.z); s1.w = fmaf(qd, b1.w, s1.w);
            s2.x = fmaf(qd, b2.x, s2.x); s2.y = fmaf(qd, b2.y, s2.y);
            s2.z = fmaf(qd, b2.z, s2.z); s2.w = fmaf(qd, b2.w, s2.w);
        }

        // ---- online softmax over this k's 192 j values --------------------
        float rmax = fmaxf(fmaxf(fmaxf(s0.x, s0.y), fmaxf(s0.z, s0.w)),
                     fmaxf(fmaxf(fmaxf(s1.x, s1.y), fmaxf(s1.z, s1.w)),
                           fmaxf(fmaxf(s2.x, s2.y), fmaxf(s2.z, s2.w))));
#pragma unroll
        for (int o = 8; o >= 1; o >>= 1)
            rmax = fmaxf(rmax, __shfl_xor_sync(0xffffffffu, rmax, o));

        float mn    = fmaxf(m, rmax);
        float alpha = __expf(m - mn);

        float4 p0, p1, p2;
        p0.x = __expf(s0.x - mn); p0.y = __expf(s0.y - mn);
        p0.z = __expf(s0.z - mn); p0.w = __expf(s0.w - mn);
        p1.x = __expf(s1.x - mn); p1.y = __expf(s1.y - mn);
        p1.z = __expf(s1.z - mn); p1.w = __expf(s1.w - mn);
        p2.x = __expf(s2.x - mn); p2.y = __expf(s2.y - mn);
        p2.z = __expf(s2.z - mn); p2.w = __expf(s2.w - mn);

        float rsum = (p0.x + p0.y + p0.z + p0.w)
                   + (p1.x + p1.y + p1.z + p1.w)
                   + (p2.x + p2.y + p2.z + p2.w);
#pragma unroll
        for (int o = 8; o >= 1; o >>= 1)
            rsum += __shfl_xor_sync(0xffffffffu, rsum, o);

        *(float4*)(ps + i * SEQ +       g * 4) = p0;
        *(float4*)(ps + i * SEQ +  64 + g * 4) = p1;
        *(float4*)(ps + i * SEQ + 128 + g * 4) = p2;

        l = l * alpha + rsum;
        m = mn;
        __syncwarp();

        // ---- pv[d] = sum_j p[j] * v1[j][d];  acc = acc*alpha + pv*v2[k,d] --
        float4 pv = make_float4(0.f,0.f,0.f,0.f);
        const float4* pr4  = (const float4*)(ps + i * SEQ);
        const float*  vbas = v1s + g * 4;
#pragma unroll 4
        for (int jq = 0; jq < 48; ++jq) {
            float4 p4 = pr4[jq];
            const float* vb = vbas + jq * 256;    // 4 j rows of 64
            float4 va = *(const float4*)(vb);
            float4 vc = *(const float4*)(vb + 64);
            float4 vd = *(const float4*)(vb + 128);
            float4 ve = *(const float4*)(vb + 192);
            pv.x = fmaf(p4.x, va.x, pv.x); pv.x = fmaf(p4.y, vc.x, pv.x);
            pv.x = fmaf(p4.z, vd.x, pv.x); pv.x = fmaf(p4.w, ve.x, pv.x);
            pv.y = fmaf(p4.x, va.y, pv.y); pv.y = fmaf(p4.y, vc.y, pv.y);
            pv.y = fmaf(p4.z, vd.y, pv.y); pv.y = fmaf(p4.w, ve.y, pv.y);
            pv.z = fmaf(p4.x, va.z, pv.z); pv.z = fmaf(p4.y, vc.z, pv.z);
            pv.z = fmaf(p4.z, vd.z, pv.z); pv.z = fmaf(p4.w, ve.z, pv.z);
            pv.w = fmaf(p4.x, va.w, pv.w); pv.w = fmaf(p4.y, vc.w, pv.w);
            pv.w = fmaf(p4.z, vd.w, pv.w); pv.w = fmaf(p4.w, ve.w, pv.w);
        }
        float4 v2v = *(const float4*)(v2b + k * DH + g * 4);
        acc.x = acc.x * alpha + pv.x * v2v.x;
        acc.y = acc.y * alpha + pv.y * v2v.y;
        acc.z = acc.z * alpha + pv.z * v2v.z;
        acc.w = acc.w * alpha + pv.w * v2v.w;
    }

    // write split-K partials
    const int row  = bh * SEQ + i0 + i;
    const int pidx = split * BHD * SEQ + row;
    if (g == 0) { pm[pidx] = m; pl[pidx] = l; }
    *(float4*)(pacc + pidx * DH + g * 4) = acc;
}

// ---------------------------------------------------------------------------
// Combine split-K partial softmax results; write [b,n,h*64+d] layout.
// ---------------------------------------------------------------------------
__global__ __launch_bounds__(64) void combine_kernel(
    const float* __restrict__ pacc, const float* __restrict__ pm,
    const float* __restrict__ pl, float* __restrict__ gattn)
{
    const int row = blockIdx.x;                 // bh*SEQ + n
    const int d   = threadIdx.x;                // 0..63
    float m0 = pm[row], m1 = pm[BHD * SEQ + row];
    float l0 = pl[row], l1 = pl[BHD * SEQ + row];
    float mm = fmaxf(m0, m1);
    float w0 = __expf(m0 - mm), w1 = __expf(m1 - mm);
    float inv = 1.0f / (w0 * l0 + w1 * l1);
    float a = (w0 * pacc[row * DH + d] + w1 * pacc[(BHD * SEQ + row) * DH + d]) * inv;

    const int bh = row / SEQ, n = row % SEQ;
    const int b = bh >> 3, h = bh & 7;
    gattn[(b * SEQ + n) * DIMM + h * DH + d] = a;
}

// ---------------------------------------------------------------------------
extern "C" void kernel_launch(void* const* d_in, const int* in_sizes, int n_in,
                              void* d_out, int out_size)
{
    (void)in_sizes; (void)n_in; (void)out_size;
    const float* tokens = (const float*)d_in[0];
    const float* w_qkv  = (const float*)d_in[1];
    const float* w_out  = (const float*)d_in[2];
    const float* qw     = (const float*)d_in[3];
    const float* k1w    = (const float*)d_in[4];
    const float* k2w    = (const float*)d_in[5];
    const float* v1w    = (const float*)d_in[6];
    const float* v2w    = (const float*)d_in[7];
    float* out = (float*)d_out;

    float *qkv, *q, *k1, *k2, *v1, *v2, *pacc, *pmv, *plv, *attn;
    cudaGetSymbolAddress((void**)&qkv,  g_qkv);
    cudaGetSymbolAddress((void**)&q,    g_q);
    cudaGetSymbolAddress((void**)&k1,   g_k1);
    cudaGetSymbolAddress((void**)&k2,   g_k2);
    cudaGetSymbolAddress((void**)&v1,   g_v1);
    cudaGetSymbolAddress((void**)&v2,   g_v2);
    cudaGetSymbolAddress((void**)&pacc, g_pacc);
    cudaGetSymbolAddress((void**)&pmv,  g_pm);
    cudaGetSymbolAddress((void**)&plv,  g_pl);
    cudaGetSymbolAddress((void**)&attn, g_attn);

    cudaFuncSetAttribute(attn_kernel,
                         cudaFuncAttributeMaxDynamicSharedMemorySize, SMEM_BYTES);

    // 1) qkv = tokens @ w_qkv^T : [384,2560]
    gemm_nt64<<<dim3(QKV_C / 64, ROWS / 64), 256>>>(tokens, w_qkv, qkv,
                                                    ROWS, QKV_C, DIMM);
    // 2) rmsnorm + split into q/k1/k2/v1/v2 [bh, n, 64]
    rmsnorm_kernel<<<ROWS * HEADS, 32>>>(qkv, qw, k1w, k2w, v1w, v2w,
                                         q, k1, k2, v1, v2);
    // 3) 2-simplicial attention, split-K online softmax
    attn_kernel<<<dim3(KSPLIT, NTILES, BHD), 256, SMEM_BYTES>>>(
        q, k1, k2, v1, v2, pacc, pmv, plv);
    // 4) combine partials -> [b,n,h*64+d]
    combine_kernel<<<BHD * SEQ, 64>>>(pacc, pmv, plv, attn);
    // 5) out = attn @ w_out^T : [384,512]
    gemm_nt64<<<dim3(DIMM / 64, ROWS / 64), 256>>>(attn, w_out, out,
                                                   ROWS, DIMM, DIMM);
}

// round 4
// speedup vs baseline: 8.3978x; 8.3978x over previous
#include <cuda_runtime.h>
#include <cuda_fp16.h>
#include <math_constants.h>
#include <cstdint>

// ---------------------------------------------------------------------------
// HigherOrderAttention — R4: tensor-core (mma.sync fp16) 2-simplicial attention
//   Fix over R3: j-chunk loop must cover all 192 j (6 chunks of 32, not 3).
// ---------------------------------------------------------------------------

#define TOK_B   2
#define SEQ     192
#define DIMM    512
#define HEADS   8
#define DH      64
#define BHD     (TOK_B * HEADS)        // 16
#define QKV_C   2560
#define ROWS    (TOK_B * SEQ)          // 384
#define KSPLIT  6
#define KRANGE  (SEQ / KSPLIT)         // 32
#define ITILE   96                     // i-rows per block (6 warps x 16)
#define NWARP   6
#define NTHR    (NWARP * 32)           // 192
#define NJC     (SEQ / 32)             // 6 j-chunks of 32

// Scratch (device globals; no runtime allocation allowed)
__device__ float  g_qkv [ROWS * QKV_C];
__device__ __half g_hq  [BHD * SEQ * DH];   // q * 0.125, fp16
__device__ __half g_hk1 [BHD * SEQ * DH];
__device__ __half g_hk2 [BHD * SEQ * DH];
__device__ __half g_hv1 [BHD * SEQ * DH];
__device__ __half g_hv2 [BHD * SEQ * DH];
__device__ float  g_pacc[KSPLIT * BHD * SEQ * DH];
__device__ float  g_pm  [KSPLIT * BHD * SEQ];
__device__ float  g_pl  [KSPLIT * BHD * SEQ];
__device__ float  g_attn[ROWS * DIMM];

// ---------------------------------------------------------------------------
// Tiled NT GEMM: C[M,Nc] = A[M,K] * B[Nc,K]^T (fp32)
// ---------------------------------------------------------------------------
__global__ __launch_bounds__(256) void gemm_nt64(
    const float* __restrict__ A, const float* __restrict__ Bm,
    float* __restrict__ C, int M, int Nc, int K)
{
    __shared__ float As[32][68];
    __shared__ float Bs[32][68];

    const int t  = threadIdx.x;
    const int ti = t >> 4;
    const int tj = t & 15;
    const int m0 = blockIdx.y * 64;
    const int n0 = blockIdx.x * 64;

    float c[4][4];
#pragma unroll
    for (int a = 0; a < 4; ++a)
#pragma unroll
        for (int b = 0; b < 4; ++b) c[a][b] = 0.f;

    for (int k0 = 0; k0 < K; k0 += 32) {
#pragma unroll
        for (int r = 0; r < 8; ++r) {
            int e   = t + 256 * r;
            int row = e >> 5;
            int kk  = e & 31;
            As[kk][row] = A [(m0 + row) * K + k0 + kk];
            Bs[kk][row] = Bm[(n0 + row) * K + k0 + kk];
        }
        __syncthreads();
#pragma unroll
        for (int kk = 0; kk < 32; ++kk) {
            float4 a4 = *(const float4*)&As[kk][ti * 4];
            float4 b4 = *(const float4*)&Bs[kk][tj * 4];
            const float av[4] = {a4.x, a4.y, a4.z, a4.w};
            const float bv[4] = {b4.x, b4.y, b4.z, b4.w};
#pragma unroll
            for (int ii = 0; ii < 4; ++ii)
#pragma unroll
                for (int jj = 0; jj < 4; ++jj)
                    c[ii][jj] = fmaf(av[ii], bv[jj], c[ii][jj]);
        }
        __syncthreads();
    }
#pragma unroll
    for (int ii = 0; ii < 4; ++ii)
#pragma unroll
        for (int jj = 0; jj < 4; ++jj)
            C[(m0 + ti * 4 + ii) * Nc + n0 + tj * 4 + jj] = c[ii][jj];
}

// ---------------------------------------------------------------------------
// RMSNorm + head split; emits fp16 (q pre-scaled by DH^-0.5 = 0.125).
// ---------------------------------------------------------------------------
__device__ __forceinline__ void rms_one_h(const float* __restrict__ x,
                                          const float* __restrict__ w,
                                          __half* __restrict__ y, int lane,
                                          float scale)
{
    float x0 = x[lane];
    float x1 = x[lane + 32];
    float ss = x0 * x0 + x1 * x1;
#pragma unroll
    for (int o = 16; o >= 1; o >>= 1)
        ss += __shfl_xor_sync(0xffffffffu, ss, o);
    float inv = rsqrtf(ss * (1.0f / 64.0f) + 1.1920929e-07f) * scale;
    y[lane]      = __float2half(x0 * inv * w[lane]);
    y[lane + 32] = __float2half(x1 * inv * w[lane + 32]);
}

__global__ __launch_bounds__(32) void rmsnorm_kernel(
    const float* __restrict__ qkv,
    const float* __restrict__ qw,  const float* __restrict__ k1w,
    const float* __restrict__ k2w, const float* __restrict__ v1w,
    const float* __restrict__ v2w,
    __half* __restrict__ hq,  __half* __restrict__ hk1, __half* __restrict__ hk2,
    __half* __restrict__ hv1, __half* __restrict__ hv2)
{
    const int id   = blockIdx.x;
    const int h    = id & 7;
    const int bn   = id >> 3;
    const int b    = bn / SEQ;
    const int n    = bn % SEQ;
    const int lane = threadIdx.x;

    const float* base = qkv + bn * QKV_C;
    const int dst = ((b * HEADS + h) * SEQ + n) * DH;

    rms_one_h(base + h * DH,              qw,  hq  + dst, lane, 0.125f);
    rms_one_h(base + 512  + h * 128,      k1w, hk1 + dst, lane, 1.0f);
    rms_one_h(base + 512  + h * 128 + DH, k2w, hk2 + dst, lane, 1.0f);
    rms_one_h(base + 1536 + h * 128,      v1w, hv1 + dst, lane, 1.0f);
    rms_one_h(base + 1536 + h * 128 + DH, v2w, hv2 + dst, lane, 1.0f);
}

// ---------------------------------------------------------------------------
// mma.sync helpers
// ---------------------------------------------------------------------------
__device__ __forceinline__ void mma16816(float c[4],
                                         unsigned a0, unsigned a1,
                                         unsigned a2, unsigned a3,
                                         unsigned b0, unsigned b1)
{
    asm volatile(
        "mma.sync.aligned.m16n8k16.row.col.f32.f16.f16.f32 "
        "{%0,%1,%2,%3},{%4,%5,%6,%7},{%8,%9},{%0,%1,%2,%3};\n"
        : "+f"(c[0]), "+f"(c[1]), "+f"(c[2]), "+f"(c[3])
        : "r"(a0), "r"(a1), "r"(a2), "r"(a3), "r"(b0), "r"(b1));
}

__device__ __forceinline__ unsigned hmul2u(unsigned a, __half2 b)
{
    __half2 av = *reinterpret_cast<__half2*>(&a);
    __half2 r  = __hmul2(av, b);
    return *reinterpret_cast<unsigned*>(&r);
}

__device__ __forceinline__ unsigned packh2(float x, float y)
{
    __half2 h = __floats2half2_rn(x, y);
    return *reinterpret_cast<unsigned*>(&h);
}

// ---------------------------------------------------------------------------
// Tensor-core attention. Block = (split, i-tile, bh). 6 warps x 16 i-rows.
// Loop: j-chunk (6 x 32 = all 192 j) outer with k1/v1 fragments register-
// resident, k inner (KRANGE), online softmax over flattened (j,k).
// ---------------------------------------------------------------------------
#define SM_K1   (SEQ * DH)       // [j][d]      12288 halves
#define SM_V1T  (DH * 200)       // [d][j] pad  12800
#define SM_Q    (ITILE * DH)     //              6144
#define SM_K2   (KRANGE * DH)    //              2048
#define SM_V2   (KRANGE * DH)    //              2048
#define ATTN_SMEM_HALVES (SM_K1 + SM_V1T + SM_Q + SM_K2 + SM_V2)
#define ATTN_SMEM_BYTES  (ATTN_SMEM_HALVES * 2)

__global__ __launch_bounds__(NTHR) void attn_mma(
    const __half* __restrict__ hq,  const __half* __restrict__ hk1,
    const __half* __restrict__ hk2, const __half* __restrict__ hv1,
    const __half* __restrict__ hv2,
    float* __restrict__ pacc, float* __restrict__ pm, float* __restrict__ pl)
{
    extern __shared__ __align__(16) __half smh[];
    __half* k1s = smh;                 // [192][64]
    __half* v1t = k1s + SM_K1;         // [64][200]  (v1 transposed, padded)
    __half* qs  = v1t + SM_V1T;        // [96][64]
    __half* k2s = qs  + SM_Q;          // [KRANGE][64]
    __half* v2s = k2s + SM_K2;         // [KRANGE][64]

    const int split = blockIdx.x;
    const int i0    = blockIdx.y * ITILE;
    const int bh    = blockIdx.z;
    const int t     = threadIdx.x;
    const int kbeg  = split * KRANGE;

    const __half* k1b = hk1 + bh * SEQ * DH;
    const __half* v1b = hv1 + bh * SEQ * DH;
    const __half* k2b = hk2 + (bh * SEQ + kbeg) * DH;
    const __half* v2b = hv2 + (bh * SEQ + kbeg) * DH;
    const __half* qb  = hq  + (bh * SEQ + i0) * DH;

    for (int e = t; e < SEQ * DH; e += NTHR) {
        int j = e >> 6, d = e & 63;
        k1s[e]            = k1b[e];
        v1t[d * 200 + j]  = v1b[e];
    }
    for (int e = t; e < ITILE * DH; e += NTHR) qs[e] = qb[e];
    for (int e = t; e < KRANGE * DH; e += NTHR) {
        k2s[e] = k2b[e];
        v2s[e] = v2b[e];
    }
    __syncthreads();

    const int warp = t >> 5;
    const int lane = t & 31;
    const int g    = lane >> 2;      // 0..7
    const int tg   = lane & 3;       // 0..3

    // q fragments (k-invariant): A[16 x 64], 4 k-chunks x 4 regs
    unsigned qa[4][4];
    {
        const __half* qr0 = qs + (warp * 16 + g) * DH;
        const __half* qr8 = qs + (warp * 16 + g + 8) * DH;
#pragma unroll
        for (int kc = 0; kc < 4; ++kc) {
            qa[kc][0] = *(const unsigned*)(qr0 + kc * 16 + 2 * tg);
            qa[kc][1] = *(const unsigned*)(qr8 + kc * 16 + 2 * tg);
            qa[kc][2] = *(const unsigned*)(qr0 + kc * 16 + 2 * tg + 8);
            qa[kc][3] = *(const unsigned*)(qr8 + kc * 16 + 2 * tg + 8);
        }
    }

    float pv[8][4];
#pragma unroll
    for (int n = 0; n < 8; ++n)
#pragma unroll
        for (int r = 0; r < 4; ++r) pv[n][r] = 0.f;

    float m0 = -CUDART_INF_F, m1 = -CUDART_INF_F;
    float l0 = 0.f, l1 = 0.f;

#pragma unroll 1
    for (int jc = 0; jc < NJC; ++jc) {
        // k-invariant B fragments for this j-chunk (register resident)
        unsigned bsf[4][4][2];   // S: k1^T [64d x 32j]: [kc(d)][nt(j)][2]
        unsigned bvf[2][8][2];   // PV: v1 [32j x 64d]:  [kc(j)][nt(d)][2]
#pragma unroll
        for (int nt = 0; nt < 4; ++nt) {
            const __half* kr = k1s + (jc * 32 + nt * 8 + g) * DH + 2 * tg;
#pragma unroll
            for (int kc = 0; kc < 4; ++kc) {
                bsf[kc][nt][0] = *(const unsigned*)(kr + kc * 16);
                bsf[kc][nt][1] = *(const unsigned*)(kr + kc * 16 + 8);
            }
        }
#pragma unroll
        for (int nt = 0; nt < 8; ++nt) {
            const __half* vr = v1t + (nt * 8 + g) * 200 + jc * 32 + 2 * tg;
#pragma unroll
            for (int kc = 0; kc < 2; ++kc) {
                bvf[kc][nt][0] = *(const unsigned*)(vr + kc * 16);
                bvf[kc][nt][1] = *(const unsigned*)(vr + kc * 16 + 8);
            }
        }

#pragma unroll 1
        for (int kk = 0; kk < KRANGE; ++kk) {
            // ---- build A = (q*scale) o k2[k] in fp16 fragments ----------
            const __half* k2r = k2s + kk * DH;
            unsigned aa[4][4];
#pragma unroll
            for (int kc = 0; kc < 4; ++kc) {
                __half2 p0 = *(const __half2*)(k2r + kc * 16 + 2 * tg);
                __half2 p1 = *(const __half2*)(k2r + kc * 16 + 2 * tg + 8);
                aa[kc][0] = hmul2u(qa[kc][0], p0);
                aa[kc][1] = hmul2u(qa[kc][1], p0);
                aa[kc][2] = hmul2u(qa[kc][2], p1);
                aa[kc][3] = hmul2u(qa[kc][3], p1);
            }

            // ---- S[16 x 32] = A @ k1chunk^T ------------------------------
            float sc[4][4];
#pragma unroll
            for (int nt = 0; nt < 4; ++nt)
#pragma unroll
                for (int r = 0; r < 4; ++r) sc[nt][r] = 0.f;
#pragma unroll
            for (int kc = 0; kc < 4; ++kc)
#pragma unroll
                for (int nt = 0; nt < 4; ++nt)
                    mma16816(sc[nt], aa[kc][0], aa[kc][1], aa[kc][2], aa[kc][3],
                             bsf[kc][nt][0], bsf[kc][nt][1]);

            // ---- online softmax (rows g, g+8) ----------------------------
            float mx0 = sc[0][0], mx1 = sc[0][2];
#pragma unroll
            for (int nt = 0; nt < 4; ++nt) {
                mx0 = fmaxf(mx0, fmaxf(sc[nt][0], sc[nt][1]));
                mx1 = fmaxf(mx1, fmaxf(sc[nt][2], sc[nt][3]));
            }
            mx0 = fmaxf(mx0, __shfl_xor_sync(0xffffffffu, mx0, 1));
            mx0 = fmaxf(mx0, __shfl_xor_sync(0xffffffffu, mx0, 2));
            mx1 = fmaxf(mx1, __shfl_xor_sync(0xffffffffu, mx1, 1));
            mx1 = fmaxf(mx1, __shfl_xor_sync(0xffffffffu, mx1, 2));

            float mn0 = fmaxf(m0, mx0);
            float mn1 = fmaxf(m1, mx1);
            float a0  = __expf(m0 - mn0);
            float a1  = __expf(m1 - mn1);

            float rs0 = 0.f, rs1 = 0.f;
#pragma unroll
            for (int nt = 0; nt < 4; ++nt) {
                sc[nt][0] = __expf(sc[nt][0] - mn0);
                sc[nt][1] = __expf(sc[nt][1] - mn0);
                sc[nt][2] = __expf(sc[nt][2] - mn1);
                sc[nt][3] = __expf(sc[nt][3] - mn1);
                rs0 += sc[nt][0] + sc[nt][1];
                rs1 += sc[nt][2] + sc[nt][3];
            }
            rs0 += __shfl_xor_sync(0xffffffffu, rs0, 1);
            rs0 += __shfl_xor_sync(0xffffffffu, rs0, 2);
            rs1 += __shfl_xor_sync(0xffffffffu, rs1, 1);
            rs1 += __shfl_xor_sync(0xffffffffu, rs1, 2);

            l0 = l0 * a0 + rs0;
            l1 = l1 * a1 + rs1;
            m0 = mn0;
            m1 = mn1;

            // rescale accumulator
#pragma unroll
            for (int nt = 0; nt < 8; ++nt) {
                pv[nt][0] *= a0; pv[nt][1] *= a0;
                pv[nt][2] *= a1; pv[nt][3] *= a1;
            }

            // ---- P fragments (reuse S c-frags as A-frags) ----------------
            unsigned pa[2][4];
#pragma unroll
            for (int kc = 0; kc < 2; ++kc) {
                pa[kc][0] = packh2(sc[2 * kc][0],     sc[2 * kc][1]);
                pa[kc][1] = packh2(sc[2 * kc][2],     sc[2 * kc][3]);
                pa[kc][2] = packh2(sc[2 * kc + 1][0], sc[2 * kc + 1][1]);
                pa[kc][3] = packh2(sc[2 * kc + 1][2], sc[2 * kc + 1][3]);
            }

            // ---- PV: out += P @ (v1 o v2[k]) -----------------------------
            const __half* v2r = v2s + kk * DH;
#pragma unroll
            for (int nt = 0; nt < 8; ++nt) {
                __half2 vdd = __half2half2(v2r[nt * 8 + g]);
#pragma unroll
                for (int kc = 0; kc < 2; ++kc) {
                    unsigned b0 = hmul2u(bvf[kc][nt][0], vdd);
                    unsigned b1 = hmul2u(bvf[kc][nt][1], vdd);
                    mma16816(pv[nt], pa[kc][0], pa[kc][1], pa[kc][2], pa[kc][3],
                             b0, b1);
                }
            }
        }
    }

    // ---- write split-K partials -----------------------------------------
    const int row0 = bh * SEQ + i0 + warp * 16 + g;
    const int row1 = row0 + 8;
    const int p0   = split * BHD * SEQ + row0;
    const int p1   = split * BHD * SEQ + row1;
    if (tg == 0) {
        pm[p0] = m0; pl[p0] = l0;
        pm[p1] = m1; pl[p1] = l1;
    }
#pragma unroll
    for (int nt = 0; nt < 8; ++nt) {
        int d = nt * 8 + 2 * tg;
        *(float2*)(pacc + p0 * DH + d) = make_float2(pv[nt][0], pv[nt][1]);
        *(float2*)(pacc + p1 * DH + d) = make_float2(pv[nt][2], pv[nt][3]);
    }
}

// ---------------------------------------------------------------------------
// Combine KSPLIT partials; write [b,n,h*64+d].
// ---------------------------------------------------------------------------
__global__ __launch_bounds__(64) void combine_kernel(
    const float* __restrict__ pacc, const float* __restrict__ pm,
    const float* __restrict__ pl, float* __restrict__ gattn)
{
    const int row = blockIdx.x;                 // bh*SEQ + n
    const int d   = threadIdx.x;

    float mm = -CUDART_INF_F;
#pragma unroll
    for (int s = 0; s < KSPLIT; ++s)
        mm = fmaxf(mm, pm[s * BHD * SEQ + row]);

    float den = 0.f, num = 0.f;
#pragma unroll
    for (int s = 0; s < KSPLIT; ++s) {
        int idx = s * BHD * SEQ + row;
        float w = __expf(pm[idx] - mm);
        den += w * pl[idx];
        num += w * pacc[idx * DH + d];
    }
    float a = num / den;

    const int bh = row / SEQ, n = row % SEQ;
    const int b = bh >> 3, h = bh & 7;
    gattn[(b * SEQ + n) * DIMM + h * DH + d] = a;
}

// ---------------------------------------------------------------------------
extern "C" void kernel_launch(void* const* d_in, const int* in_sizes, int n_in,
                              void* d_out, int out_size)
{
    (void)in_sizes; (void)n_in; (void)out_size;
    const float* tokens = (const float*)d_in[0];
    const float* w_qkv  = (const float*)d_in[1];
    const float* w_out  = (const float*)d_in[2];
    const float* qw     = (const float*)d_in[3];
    const float* k1w    = (const float*)d_in[4];
    const float* k2w    = (const float*)d_in[5];
    const float* v1w    = (const float*)d_in[6];
    const float* v2w    = (const float*)d_in[7];
    float* out = (float*)d_out;

    float *qkv, *pacc, *pmv, *plv, *attn;
    __half *hq, *hk1, *hk2, *hv1, *hv2;
    cudaGetSymbolAddress((void**)&qkv,  g_qkv);
    cudaGetSymbolAddress((void**)&hq,   g_hq);
    cudaGetSymbolAddress((void**)&hk1,  g_hk1);
    cudaGetSymbolAddress((void**)&hk2,  g_hk2);
    cudaGetSymbolAddress((void**)&hv1,  g_hv1);
    cudaGetSymbolAddress((void**)&hv2,  g_hv2);
    cudaGetSymbolAddress((void**)&pacc, g_pacc);
    cudaGetSymbolAddress((void**)&pmv,  g_pm);
    cudaGetSymbolAddress((void**)&plv,  g_pl);
    cudaGetSymbolAddress((void**)&attn, g_attn);

    cudaFuncSetAttribute(attn_mma,
                         cudaFuncAttributeMaxDynamicSharedMemorySize,
                         ATTN_SMEM_BYTES);

    // 1) qkv = tokens @ w_qkv^T : [384,2560]
    gemm_nt64<<<dim3(QKV_C / 64, ROWS / 64), 256>>>(tokens, w_qkv, qkv,
                                                    ROWS, QKV_C, DIMM);
    // 2) rmsnorm + split -> fp16 q*scale, k1, k2, v1, v2 [bh, n, 64]
    rmsnorm_kernel<<<ROWS * HEADS, 32>>>(qkv, qw, k1w, k2w, v1w, v2w,
                                         hq, hk1, hk2, hv1, hv2);
    // 3) tensor-core 2-simplicial attention, split-K online softmax
    attn_mma<<<dim3(KSPLIT, SEQ / ITILE, BHD), NTHR, ATTN_SMEM_BYTES>>>(
        hq, hk1, hk2, hv1, hv2, pacc, pmv, plv);
    // 4) combine partials -> [b,n,h*64+d]
    combine_kernel<<<BHD * SEQ, 64>>>(pacc, pmv, plv, attn);
    // 5) out = attn @ w_out^T : [384,512]
    gemm_nt64<<<dim3(DIMM / 64, ROWS / 64), 256>>>(attn, w_out, out,
                                                   ROWS, DIMM, DIMM);
}

// round 5
// speedup vs baseline: 13.9181x; 1.6574x over previous
#include <cuda_runtime.h>
#include <cuda_fp16.h>
#include <math_constants.h>
#include <cstdint>

// ---------------------------------------------------------------------------
// HigherOrderAttention — R5:
//   * fp16 hi/lo split tensor-core GEMMs (fp32-quality) for QKV and out
//   * static-max softmax (no online rescale), l via all-ones mma column
//   * ex2.approx.f16x2 exp (log2e folded into q scale)
// ---------------------------------------------------------------------------

#define TOK_B   2
#define SEQ     192
#define DIMM    512
#define HEADS   8
#define DH      64
#define BHD     (TOK_B * HEADS)        // 16
#define QKV_C   2560
#define ROWS    (TOK_B * SEQ)          // 384
#define KSPLIT  8
#define KRANGE  (SEQ / KSPLIT)         // 24
#define ITILE   64                     // i-rows per block (4 warps x 16)
#define NWARP   4
#define NTHR    (NWARP * 32)           // 128
#define NJC     (SEQ / 32)             // 6 j-chunks of 32

// static softmax max (natural units) = 5; in log2 units:
#define M_LOG2  7.2134752f             // 5 * log2(e)
#define QSCALE  0.18033688f            // 0.125 * log2(e)

// Scratch (device globals; no runtime allocation allowed)
__device__ float  g_qkv [ROWS * QKV_C];
__device__ __half g_hq  [BHD * SEQ * DH];   // q * 0.125 * log2e
__device__ __half g_hk1 [BHD * SEQ * DH];
__device__ __half g_hk2 [BHD * SEQ * DH];
__device__ __half g_hv1 [BHD * SEQ * DH];
__device__ __half g_hv2 [BHD * SEQ * DH];
__device__ float  g_pacc[KSPLIT * BHD * SEQ * DH];
__device__ float  g_pl  [KSPLIT * BHD * SEQ];
__device__ float  g_attn[ROWS * DIMM];

// ---------------------------------------------------------------------------
// mma.sync helpers
// ---------------------------------------------------------------------------
__device__ __forceinline__ void mma16816(float c[4],
                                         unsigned a0, unsigned a1,
                                         unsigned a2, unsigned a3,
                                         unsigned b0, unsigned b1)
{
    asm volatile(
        "mma.sync.aligned.m16n8k16.row.col.f32.f16.f16.f32 "
        "{%0,%1,%2,%3},{%4,%5,%6,%7},{%8,%9},{%0,%1,%2,%3};\n"
        : "+f"(c[0]), "+f"(c[1]), "+f"(c[2]), "+f"(c[3])
        : "r"(a0), "r"(a1), "r"(a2), "r"(a3), "r"(b0), "r"(b1));
}

__device__ __forceinline__ unsigned hmul2u(unsigned a, __half2 b)
{
    __half2 av = *reinterpret_cast<__half2*>(&a);
    __half2 r  = __hmul2(av, b);
    return *reinterpret_cast<unsigned*>(&r);
}

// pack(a,b) -> subtract M (log2) -> 2^x in fp16x2
__device__ __forceinline__ unsigned p2exp(float a, float b, __half2 mbias)
{
    __half2 h = __floats2half2_rn(a, b);
    h = __hadd2(h, mbias);
    unsigned x = *reinterpret_cast<unsigned*>(&h);
    unsigned r;
    asm("ex2.approx.f16x2 %0, %1;" : "=r"(r) : "r"(x));
    return r;
}

// ---------------------------------------------------------------------------
// Tensor-core NT GEMM with fp16 hi/lo split (near-fp32 accuracy):
//   C[M,N] = A[M,K] @ B[N,K]^T,  A/B/C fp32, M,N mult of 64, K mult of 32.
// Block 64x64, 256 threads (8 warps as 4m x 2n, warp tile 16m x 32n).
// ---------------------------------------------------------------------------
__global__ __launch_bounds__(256) void gemm_nt_tc(
    const float* __restrict__ A, const float* __restrict__ B,
    float* __restrict__ C, int M, int N, int K)
{
    __shared__ __half Ah[64 * 36], Al[64 * 36];
    __shared__ __half Bh[64 * 36], Bl[64 * 36];

    const int t    = threadIdx.x;
    const int m0   = blockIdx.y * 64;
    const int n0   = blockIdx.x * 64;
    const int warp = t >> 5;
    const int lane = t & 31;
    const int g    = lane >> 2;
    const int tg   = lane & 3;
    const int wm   = warp >> 1;   // 0..3
    const int wn   = warp & 1;    // 0..1

    float c[4][4];
#pragma unroll
    for (int a = 0; a < 4; ++a)
#pragma unroll
        for (int b = 0; b < 4; ++b) c[a][b] = 0.f;

    for (int k0 = 0; k0 < K; k0 += 32) {
        __syncthreads();
#pragma unroll
        for (int r = 0; r < 2; ++r) {
            int e   = t + 256 * r;         // 0..511
            int row = e >> 3;
            int kq  = (e & 7) * 4;

            float4 a4 = *(const float4*)(A + (size_t)(m0 + row) * K + k0 + kq);
            __half ax = __float2half_rn(a4.x), ay = __float2half_rn(a4.y);
            __half az = __float2half_rn(a4.z), aw = __float2half_rn(a4.w);
            *(__half2*)(Ah + row * 36 + kq)     = __halves2half2(ax, ay);
            *(__half2*)(Ah + row * 36 + kq + 2) = __halves2half2(az, aw);
            *(__half2*)(Al + row * 36 + kq)     = __halves2half2(
                __float2half_rn(a4.x - __half2float(ax)),
                __float2half_rn(a4.y - __half2float(ay)));
            *(__half2*)(Al + row * 36 + kq + 2) = __halves2half2(
                __float2half_rn(a4.z - __half2float(az)),
                __float2half_rn(a4.w - __half2float(aw)));

            float4 b4 = *(const float4*)(B + (size_t)(n0 + row) * K + k0 + kq);
            __half bx = __float2half_rn(b4.x), by = __float2half_rn(b4.y);
            __half bz = __float2half_rn(b4.z), bw = __float2half_rn(b4.w);
            *(__half2*)(Bh + row * 36 + kq)     = __halves2half2(bx, by);
            *(__half2*)(Bh + row * 36 + kq + 2) = __halves2half2(bz, bw);
            *(__half2*)(Bl + row * 36 + kq)     = __halves2half2(
                __float2half_rn(b4.x - __half2float(bx)),
                __float2half_rn(b4.y - __half2float(by)));
            *(__half2*)(Bl + row * 36 + kq + 2) = __halves2half2(
                __float2half_rn(b4.z - __half2float(bz)),
                __float2half_rn(b4.w - __half2float(bw)));
        }
        __syncthreads();

#pragma unroll
        for (int kc = 0; kc < 2; ++kc) {
            const int ko = kc * 16 + 2 * tg;
            const __half* ar0 = Ah + (wm * 16 + g) * 36 + ko;
            const __half* ar8 = ar0 + 8 * 36;
            const __half* lr0 = Al + (wm * 16 + g) * 36 + ko;
            const __half* lr8 = lr0 + 8 * 36;

            unsigned ah0 = *(const unsigned*)(ar0);
            unsigned ah1 = *(const unsigned*)(ar8);
            unsigned ah2 = *(const unsigned*)(ar0 + 8);
            unsigned ah3 = *(const unsigned*)(ar8 + 8);
            unsigned al0 = *(const unsigned*)(lr0);
            unsigned al1 = *(const unsigned*)(lr8);
            unsigned al2 = *(const unsigned*)(lr0 + 8);
            unsigned al3 = *(const unsigned*)(lr8 + 8);

#pragma unroll
            for (int nt = 0; nt < 4; ++nt) {
                const int nrow = wn * 32 + nt * 8 + g;
                unsigned bh0 = *(const unsigned*)(Bh + nrow * 36 + ko);
                unsigned bh1 = *(const unsigned*)(Bh + nrow * 36 + ko + 8);
                unsigned bl0 = *(const unsigned*)(Bl + nrow * 36 + ko);
                unsigned bl1 = *(const unsigned*)(Bl + nrow * 36 + ko + 8);
                mma16816(c[nt], ah0, ah1, ah2, ah3, bh0, bh1);
                mma16816(c[nt], ah0, ah1, ah2, ah3, bl0, bl1);
                mma16816(c[nt], al0, al1, al2, al3, bh0, bh1);
            }
        }
    }

    const int row0 = m0 + wm * 16 + g;
    const int row1 = row0 + 8;
#pragma unroll
    for (int nt = 0; nt < 4; ++nt) {
        const int col = n0 + wn * 32 + nt * 8 + 2 * tg;
        *(float2*)(C + (size_t)row0 * N + col) = make_float2(c[nt][0], c[nt][1]);
        *(float2*)(C + (size_t)row1 * N + col) = make_float2(c[nt][2], c[nt][3]);
    }
}

// ---------------------------------------------------------------------------
// RMSNorm + head split; emits fp16 (q pre-scaled by 0.125*log2e).
// 8 warps per block, one (bn,h) per warp.
// ---------------------------------------------------------------------------
__device__ __forceinline__ void rms_one_h(const float* __restrict__ x,
                                          const float* __restrict__ w,
                                          __half* __restrict__ y, int lane,
                                          float scale)
{
    float x0 = x[lane];
    float x1 = x[lane + 32];
    float ss = x0 * x0 + x1 * x1;
#pragma unroll
    for (int o = 16; o >= 1; o >>= 1)
        ss += __shfl_xor_sync(0xffffffffu, ss, o);
    float inv = rsqrtf(ss * (1.0f / 64.0f) + 1.1920929e-07f) * scale;
    y[lane]      = __float2half(x0 * inv * w[lane]);
    y[lane + 32] = __float2half(x1 * inv * w[lane + 32]);
}

__global__ __launch_bounds__(256) void rmsnorm_kernel(
    const float* __restrict__ qkv,
    const float* __restrict__ qw,  const float* __restrict__ k1w,
    const float* __restrict__ k2w, const float* __restrict__ v1w,
    const float* __restrict__ v2w,
    __half* __restrict__ hq,  __half* __restrict__ hk1, __half* __restrict__ hk2,
    __half* __restrict__ hv1, __half* __restrict__ hv2)
{
    const int wid  = threadIdx.x >> 5;
    const int lane = threadIdx.x & 31;
    const int id   = blockIdx.x * 8 + wid;   // (b*SEQ+n)*HEADS + h
    const int h    = id & 7;
    const int bn   = id >> 3;
    const int b    = bn / SEQ;
    const int n    = bn % SEQ;

    const float* base = qkv + bn * QKV_C;
    const int dst = ((b * HEADS + h) * SEQ + n) * DH;

    rms_one_h(base + h * DH,              qw,  hq  + dst, lane, QSCALE);
    rms_one_h(base + 512  + h * 128,      k1w, hk1 + dst, lane, 1.0f);
    rms_one_h(base + 512  + h * 128 + DH, k2w, hk2 + dst, lane, 1.0f);
    rms_one_h(base + 1536 + h * 128,      v1w, hv1 + dst, lane, 1.0f);
    rms_one_h(base + 1536 + h * 128 + DH, v2w, hv2 + dst, lane, 1.0f);
}

// ---------------------------------------------------------------------------
// Tensor-core attention, static-max softmax.
// Block = (split, i-tile, bh). 4 warps x 16 i-rows = 64 rows.
// ---------------------------------------------------------------------------
#define K1_STRIDE 72
#define SM_K1   (SEQ * K1_STRIDE)  // 13824 halves
#define SM_V1T  (DH * 200)         // 12800
#define SM_Q    (ITILE * DH)       //  4096
#define SM_K2   (KRANGE * DH)      //  1536
#define SM_V2   (KRANGE * DH)      //  1536
#define ATTN_SMEM_HALVES (SM_K1 + SM_V1T + SM_Q + SM_K2 + SM_V2)
#define ATTN_SMEM_BYTES  (ATTN_SMEM_HALVES * 2)

__global__ __launch_bounds__(NTHR, 3) void attn_mma(
    const __half* __restrict__ hq,  const __half* __restrict__ hk1,
    const __half* __restrict__ hk2, const __half* __restrict__ hv1,
    const __half* __restrict__ hv2,
    float* __restrict__ pacc, float* __restrict__ pl)
{
    extern __shared__ __align__(16) __half smh[];
    __half* k1s = smh;                 // [192][72]
    __half* v1t = k1s + SM_K1;         // [64][200]  (v1 transposed, padded)
    __half* qs  = v1t + SM_V1T;        // [64][64]
    __half* k2s = qs  + SM_Q;          // [KRANGE][64]
    __half* v2s = k2s + SM_K2;         // [KRANGE][64]

    const int split = blockIdx.x;
    const int i0    = blockIdx.y * ITILE;
    const int bh    = blockIdx.z;
    const int t     = threadIdx.x;
    const int kbeg  = split * KRANGE;

    const __half* k1b = hk1 + bh * SEQ * DH;
    const __half* v1b = hv1 + bh * SEQ * DH;
    const __half* k2b = hk2 + (bh * SEQ + kbeg) * DH;
    const __half* v2b = hv2 + (bh * SEQ + kbeg) * DH;
    const __half* qb  = hq  + (bh * SEQ + i0) * DH;

    for (int e = t; e < SEQ * DH; e += NTHR) {
        int j = e >> 6, d = e & 63;
        k1s[j * K1_STRIDE + d] = k1b[e];
        v1t[d * 200 + j]       = v1b[e];
    }
    for (int e = t; e < ITILE * DH; e += NTHR) qs[e] = qb[e];
    for (int e = t; e < KRANGE * DH; e += NTHR) {
        k2s[e] = k2b[e];
        v2s[e] = v2b[e];
    }
    __syncthreads();

    const int warp = t >> 5;
    const int lane = t & 31;
    const int g    = lane >> 2;      // 0..7
    const int tg   = lane & 3;       // 0..3

    const __half2  mbias = __half2half2(__float2half(-M_LOG2));
    const unsigned BONES = 0x3C003C00u;   // (1.0h, 1.0h)

    // q fragments (k-invariant): A[16 x 64], 4 k-chunks x 4 regs
    unsigned qa[4][4];
    {
        const __half* qr0 = qs + (warp * 16 + g) * DH;
        const __half* qr8 = qs + (warp * 16 + g + 8) * DH;
#pragma unroll
        for (int kc = 0; kc < 4; ++kc) {
            qa[kc][0] = *(const unsigned*)(qr0 + kc * 16 + 2 * tg);
            qa[kc][1] = *(const unsigned*)(qr8 + kc * 16 + 2 * tg);
            qa[kc][2] = *(const unsigned*)(qr0 + kc * 16 + 2 * tg + 8);
            qa[kc][3] = *(const unsigned*)(qr8 + kc * 16 + 2 * tg + 8);
        }
    }

    float pv[8][4];
#pragma unroll
    for (int n = 0; n < 8; ++n)
#pragma unroll
        for (int r = 0; r < 4; ++r) pv[n][r] = 0.f;
    float cl[4] = {0.f, 0.f, 0.f, 0.f};   // l accumulator (ones-column mma)

#pragma unroll 1
    for (int jc = 0; jc < NJC; ++jc) {
        // k-invariant B fragments for this j-chunk (register resident)
        unsigned bsf[4][4][2];   // S: k1^T [64d x 32j]
        unsigned bvf[2][8][2];   // PV: v1 [32j x 64d]
#pragma unroll
        for (int nt = 0; nt < 4; ++nt) {
            const __half* kr = k1s + (jc * 32 + nt * 8 + g) * K1_STRIDE + 2 * tg;
#pragma unroll
            for (int kc = 0; kc < 4; ++kc) {
                bsf[kc][nt][0] = *(const unsigned*)(kr + kc * 16);
                bsf[kc][nt][1] = *(const unsigned*)(kr + kc * 16 + 8);
            }
        }
#pragma unroll
        for (int nt = 0; nt < 8; ++nt) {
            const __half* vr = v1t + (nt * 8 + g) * 200 + jc * 32 + 2 * tg;
#pragma unroll
            for (int kc = 0; kc < 2; ++kc) {
                bvf[kc][nt][0] = *(const unsigned*)(vr + kc * 16);
                bvf[kc][nt][1] = *(const unsigned*)(vr + kc * 16 + 8);
            }
        }

#pragma unroll 1
        for (int kk = 0; kk < KRANGE; ++kk) {
            // ---- A = q o k2[k] (fp16), log2e/scale pre-folded ------------
            const __half* k2r = k2s + kk * DH;
            unsigned aa[4][4];
#pragma unroll
            for (int kc = 0; kc < 4; ++kc) {
                __half2 p0 = *(const __half2*)(k2r + kc * 16 + 2 * tg);
                __half2 p1 = *(const __half2*)(k2r + kc * 16 + 2 * tg + 8);
                aa[kc][0] = hmul2u(qa[kc][0], p0);
                aa[kc][1] = hmul2u(qa[kc][1], p0);
                aa[kc][2] = hmul2u(qa[kc][2], p1);
                aa[kc][3] = hmul2u(qa[kc][3], p1);
            }

            // ---- S[16 x 32] (log2 units) ---------------------------------
            float sc[4][4];
#pragma unroll
            for (int nt = 0; nt < 4; ++nt)
#pragma unroll
                for (int r = 0; r < 4; ++r) sc[nt][r] = 0.f;
#pragma unroll
            for (int kc = 0; kc < 4; ++kc)
#pragma unroll
                for (int nt = 0; nt < 4; ++nt)
                    mma16816(sc[nt], aa[kc][0], aa[kc][1], aa[kc][2], aa[kc][3],
                             bsf[kc][nt][0], bsf[kc][nt][1]);

            // ---- p = 2^(s - M) in fp16x2, static max ---------------------
            unsigned pa[2][4];
#pragma unroll
            for (int kc = 0; kc < 2; ++kc) {
                pa[kc][0] = p2exp(sc[2 * kc][0],     sc[2 * kc][1],     mbias);
                pa[kc][1] = p2exp(sc[2 * kc][2],     sc[2 * kc][3],     mbias);
                pa[kc][2] = p2exp(sc[2 * kc + 1][0], sc[2 * kc + 1][1], mbias);
                pa[kc][3] = p2exp(sc[2 * kc + 1][2], sc[2 * kc + 1][3], mbias);
            }

            // ---- l += P @ ones (exact fp32 row sums via mma) -------------
            mma16816(cl, pa[0][0], pa[0][1], pa[0][2], pa[0][3], BONES, BONES);
            mma16816(cl, pa[1][0], pa[1][1], pa[1][2], pa[1][3], BONES, BONES);

            // ---- PV: out += P @ (v1 o v2[k]) -----------------------------
            const __half* v2r = v2s + kk * DH;
#pragma unroll
            for (int nt = 0; nt < 8; ++nt) {
                __half2 vdd = __half2half2(v2r[nt * 8 + g]);
#pragma unroll
                for (int kc = 0; kc < 2; ++kc) {
                    unsigned b0 = hmul2u(bvf[kc][nt][0], vdd);
                    unsigned b1 = hmul2u(bvf[kc][nt][1], vdd);
                    mma16816(pv[nt], pa[kc][0], pa[kc][1], pa[kc][2], pa[kc][3],
                             b0, b1);
                }
            }
        }
    }

    // ---- write split-K partials (no max needed: static) -------------------
    const int row0 = bh * SEQ + i0 + warp * 16 + g;
    const int row1 = row0 + 8;
    const int p0   = split * BHD * SEQ + row0;
    const int p1   = split * BHD * SEQ + row1;
    if (tg == 0) {
        pl[p0] = cl[0];
        pl[p1] = cl[2];
    }
#pragma unroll
    for (int nt = 0; nt < 8; ++nt) {
        int d = nt * 8 + 2 * tg;
        *(float2*)(pacc + (size_t)p0 * DH + d) = make_float2(pv[nt][0], pv[nt][1]);
        *(float2*)(pacc + (size_t)p1 * DH + d) = make_float2(pv[nt][2], pv[nt][3]);
    }
}

// ---------------------------------------------------------------------------
// Combine KSPLIT partials (same static max -> plain sums); [b,n,h*64+d].
// ---------------------------------------------------------------------------
__global__ __launch_bounds__(64) void combine_kernel(
    const float* __restrict__ pacc, const float* __restrict__ pl,
    float* __restrict__ gattn)
{
    const int row = blockIdx.x;                 // bh*SEQ + n
    const int d   = threadIdx.x;

    float den = 0.f, num = 0.f;
#pragma unroll
    for (int s = 0; s < KSPLIT; ++s) {
        int idx = s * BHD * SEQ + row;
        den += pl[idx];
        num += pacc[(size_t)idx * DH + d];
    }
    float a = num / den;

    const int bh = row / SEQ, n = row % SEQ;
    const int b = bh >> 3, h = bh & 7;
    gattn[(b * SEQ + n) * DIMM + h * DH + d] = a;
}

// ---------------------------------------------------------------------------
extern "C" void kernel_launch(void* const* d_in, const int* in_sizes, int n_in,
                              void* d_out, int out_size)
{
    (void)in_sizes; (void)n_in; (void)out_size;
    const float* tokens = (const float*)d_in[0];
    const float* w_qkv  = (const float*)d_in[1];
    const float* w_out  = (const float*)d_in[2];
    const float* qw     = (const float*)d_in[3];
    const float* k1w    = (const float*)d_in[4];
    const float* k2w    = (const float*)d_in[5];
    const float* v1w    = (const float*)d_in[6];
    const float* v2w    = (const float*)d_in[7];
    float* out = (float*)d_out;

    float *qkv, *pacc, *plv, *attn;
    __half *hq, *hk1, *hk2, *hv1, *hv2;
    cudaGetSymbolAddress((void**)&qkv,  g_qkv);
    cudaGetSymbolAddress((void**)&hq,   g_hq);
    cudaGetSymbolAddress((void**)&hk1,  g_hk1);
    cudaGetSymbolAddress((void**)&hk2,  g_hk2);
    cudaGetSymbolAddress((void**)&hv1,  g_hv1);
    cudaGetSymbolAddress((void**)&hv2,  g_hv2);
    cudaGetSymbolAddress((void**)&pacc, g_pacc);
    cudaGetSymbolAddress((void**)&plv,  g_pl);
    cudaGetSymbolAddress((void**)&attn, g_attn);

    cudaFuncSetAttribute(attn_mma,
                         cudaFuncAttributeMaxDynamicSharedMemorySize,
                         ATTN_SMEM_BYTES);

    // 1) qkv = tokens @ w_qkv^T : [384,2560]  (fp16-split tensor GEMM)
    gemm_nt_tc<<<dim3(QKV_C / 64, ROWS / 64), 256>>>(tokens, w_qkv, qkv,
                                                     ROWS, QKV_C, DIMM);
    // 2) rmsnorm + split -> fp16 q*qscale, k1, k2, v1, v2 [bh, n, 64]
    rmsnorm_kernel<<<ROWS * HEADS / 8, 256>>>(qkv, qw, k1w, k2w, v1w, v2w,
                                              hq, hk1, hk2, hv1, hv2);
    // 3) tensor-core 2-simplicial attention, static-max split-K
    attn_mma<<<dim3(KSPLIT, SEQ / ITILE, BHD), NTHR, ATTN_SMEM_BYTES>>>(
        hq, hk1, hk2, hv1, hv2, pacc, plv);
    // 4) combine partials -> [b,n,h*64+d]
    combine_kernel<<<BHD * SEQ, 64>>>(pacc, plv, attn);
    // 5) out = attn @ w_out^T : [384,512]
    gemm_nt_tc<<<dim3(DIMM / 64, ROWS / 64), 256>>>(attn, w_out, out,
                                                    ROWS, DIMM, DIMM);
}

// round 6
// speedup vs baseline: 14.4868x; 1.0409x over previous
#include <cuda_runtime.h>
#include <cuda_fp16.h>
#include <math_constants.h>
#include <cstdint>

// ---------------------------------------------------------------------------
// HigherOrderAttention — R6:
//   * p2exp: bias subtract in fp32 BEFORE fp16 cvt (fixes rel_err margin)
//   * KSPLIT 8 -> 6: even 2-blocks/SM distribution (makespan 432->384 steps)
//   * combine: 256-thread blocks
// ---------------------------------------------------------------------------

#define TOK_B   2
#define SEQ     192
#define DIMM    512
#define HEADS   8
#define DH      64
#define BHD     (TOK_B * HEADS)        // 16
#define QKV_C   2560
#define ROWS    (TOK_B * SEQ)          // 384
#define KSPLIT  6
#define KRANGE  (SEQ / KSPLIT)         // 32
#define ITILE   64                     // i-rows per block (4 warps x 16)
#define NWARP   4
#define NTHR    (NWARP * 32)           // 128
#define NJC     (SEQ / 32)             // 6 j-chunks of 32

// static softmax max (natural units) = 5; in log2 units:
#define M_LOG2  7.2134752f             // 5 * log2(e)
#define QSCALE  0.18033688f            // 0.125 * log2(e)

// Scratch (device globals; no runtime allocation allowed)
__device__ float  g_qkv [ROWS * QKV_C];
__device__ __half g_hq  [BHD * SEQ * DH];   // q * 0.125 * log2e
__device__ __half g_hk1 [BHD * SEQ * DH];
__device__ __half g_hk2 [BHD * SEQ * DH];
__device__ __half g_hv1 [BHD * SEQ * DH];
__device__ __half g_hv2 [BHD * SEQ * DH];
__device__ float  g_pacc[KSPLIT * BHD * SEQ * DH];
__device__ float  g_pl  [KSPLIT * BHD * SEQ];
__device__ float  g_attn[ROWS * DIMM];

// ---------------------------------------------------------------------------
// mma.sync helpers
// ---------------------------------------------------------------------------
__device__ __forceinline__ void mma16816(float c[4],
                                         unsigned a0, unsigned a1,
                                         unsigned a2, unsigned a3,
                                         unsigned b0, unsigned b1)
{
    asm volatile(
        "mma.sync.aligned.m16n8k16.row.col.f32.f16.f16.f32 "
        "{%0,%1,%2,%3},{%4,%5,%6,%7},{%8,%9},{%0,%1,%2,%3};\n"
        : "+f"(c[0]), "+f"(c[1]), "+f"(c[2]), "+f"(c[3])
        : "r"(a0), "r"(a1), "r"(a2), "r"(a3), "r"(b0), "r"(b1));
}

__device__ __forceinline__ unsigned hmul2u(unsigned a, __half2 b)
{
    __half2 av = *reinterpret_cast<__half2*>(&a);
    __half2 r  = __hmul2(av, b);
    return *reinterpret_cast<unsigned*>(&r);
}

// (a,b) in log2 units -> subtract M in fp32 -> cvt fp16x2 -> 2^x
__device__ __forceinline__ unsigned p2exp(float a, float b)
{
    __half2 h = __floats2half2_rn(a - M_LOG2, b - M_LOG2);
    unsigned x = *reinterpret_cast<unsigned*>(&h);
    unsigned r;
    asm("ex2.approx.f16x2 %0, %1;" : "=r"(r) : "r"(x));
    return r;
}

// ---------------------------------------------------------------------------
// Tensor-core NT GEMM with fp16 hi/lo split (near-fp32 accuracy):
//   C[M,N] = A[M,K] @ B[N,K]^T,  A/B/C fp32, M,N mult of 64, K mult of 32.
// Block 64x64, 256 threads (8 warps as 4m x 2n, warp tile 16m x 32n).
// ---------------------------------------------------------------------------
__global__ __launch_bounds__(256) void gemm_nt_tc(
    const float* __restrict__ A, const float* __restrict__ B,
    float* __restrict__ C, int M, int N, int K)
{
    __shared__ __half Ah[64 * 36], Al[64 * 36];
    __shared__ __half Bh[64 * 36], Bl[64 * 36];

    const int t    = threadIdx.x;
    const int m0   = blockIdx.y * 64;
    const int n0   = blockIdx.x * 64;
    const int warp = t >> 5;
    const int lane = t & 31;
    const int g    = lane >> 2;
    const int tg   = lane & 3;
    const int wm   = warp >> 1;   // 0..3
    const int wn   = warp & 1;    // 0..1

    float c[4][4];
#pragma unroll
    for (int a = 0; a < 4; ++a)
#pragma unroll
        for (int b = 0; b < 4; ++b) c[a][b] = 0.f;

    for (int k0 = 0; k0 < K; k0 += 32) {
        __syncthreads();
#pragma unroll
        for (int r = 0; r < 2; ++r) {
            int e   = t + 256 * r;         // 0..511
            int row = e >> 3;
            int kq  = (e & 7) * 4;

            float4 a4 = *(const float4*)(A + (size_t)(m0 + row) * K + k0 + kq);
            __half ax = __float2half_rn(a4.x), ay = __float2half_rn(a4.y);
            __half az = __float2half_rn(a4.z), aw = __float2half_rn(a4.w);
            *(__half2*)(Ah + row * 36 + kq)     = __halves2half2(ax, ay);
            *(__half2*)(Ah + row * 36 + kq + 2) = __halves2half2(az, aw);
            *(__half2*)(Al + row * 36 + kq)     = __halves2half2(
                __float2half_rn(a4.x - __half2float(ax)),
                __float2half_rn(a4.y - __half2float(ay)));
            *(__half2*)(Al + row * 36 + kq + 2) = __halves2half2(
                __float2half_rn(a4.z - __half2float(az)),
                __float2half_rn(a4.w - __half2float(aw)));

            float4 b4 = *(const float4*)(B + (size_t)(n0 + row) * K + k0 + kq);
            __half bx = __float2half_rn(b4.x), by = __float2half_rn(b4.y);
            __half bz = __float2half_rn(b4.z), bw = __float2half_rn(b4.w);
            *(__half2*)(Bh + row * 36 + kq)     = __halves2half2(bx, by);
            *(__half2*)(Bh + row * 36 + kq + 2) = __halves2half2(bz, bw);
            *(__half2*)(Bl + row * 36 + kq)     = __halves2half2(
                __float2half_rn(b4.x - __half2float(bx)),
                __float2half_rn(b4.y - __half2float(by)));
            *(__half2*)(Bl + row * 36 + kq + 2) = __halves2half2(
                __float2half_rn(b4.z - __half2float(bz)),
                __float2half_rn(b4.w - __half2float(bw)));
        }
        __syncthreads();

#pragma unroll
        for (int kc = 0; kc < 2; ++kc) {
            const int ko = kc * 16 + 2 * tg;
            const __half* ar0 = Ah + (wm * 16 + g) * 36 + ko;
            const __half* ar8 = ar0 + 8 * 36;
            const __half* lr0 = Al + (wm * 16 + g) * 36 + ko;
            const __half* lr8 = lr0 + 8 * 36;

            unsigned ah0 = *(const unsigned*)(ar0);
            unsigned ah1 = *(const unsigned*)(ar8);
            unsigned ah2 = *(const unsigned*)(ar0 + 8);
            unsigned ah3 = *(const unsigned*)(ar8 + 8);
            unsigned al0 = *(const unsigned*)(lr0);
            unsigned al1 = *(const unsigned*)(lr8);
            unsigned al2 = *(const unsigned*)(lr0 + 8);
            unsigned al3 = *(const unsigned*)(lr8 + 8);

#pragma unroll
            for (int nt = 0; nt < 4; ++nt) {
                const int nrow = wn * 32 + nt * 8 + g;
                unsigned bh0 = *(const unsigned*)(Bh + nrow * 36 + ko);
                unsigned bh1 = *(const unsigned*)(Bh + nrow * 36 + ko + 8);
                unsigned bl0 = *(const unsigned*)(Bl + nrow * 36 + ko);
                unsigned bl1 = *(const unsigned*)(Bl + nrow * 36 + ko + 8);
                mma16816(c[nt], ah0, ah1, ah2, ah3, bh0, bh1);
                mma16816(c[nt], ah0, ah1, ah2, ah3, bl0, bl1);
                mma16816(c[nt], al0, al1, al2, al3, bh0, bh1);
            }
        }
    }

    const int row0 = m0 + wm * 16 + g;
    const int row1 = row0 + 8;
#pragma unroll
    for (int nt = 0; nt < 4; ++nt) {
        const int col = n0 + wn * 32 + nt * 8 + 2 * tg;
        *(float2*)(C + (size_t)row0 * N + col) = make_float2(c[nt][0], c[nt][1]);
        *(float2*)(C + (size_t)row1 * N + col) = make_float2(c[nt][2], c[nt][3]);
    }
}

// ---------------------------------------------------------------------------
// RMSNorm + head split; emits fp16 (q pre-scaled by 0.125*log2e).
// 8 warps per block, one (bn,h) per warp.
// ---------------------------------------------------------------------------
__device__ __forceinline__ void rms_one_h(const float* __restrict__ x,
                                          const float* __restrict__ w,
                                          __half* __restrict__ y, int lane,
                                          float scale)
{
    float x0 = x[lane];
    float x1 = x[lane + 32];
    float ss = x0 * x0 + x1 * x1;
#pragma unroll
    for (int o = 16; o >= 1; o >>= 1)
        ss += __shfl_xor_sync(0xffffffffu, ss, o);
    float inv = rsqrtf(ss * (1.0f / 64.0f) + 1.1920929e-07f) * scale;
    y[lane]      = __float2half(x0 * inv * w[lane]);
    y[lane + 32] = __float2half(x1 * inv * w[lane + 32]);
}

__global__ __launch_bounds__(256) void rmsnorm_kernel(
    const float* __restrict__ qkv,
    const float* __restrict__ qw,  const float* __restrict__ k1w,
    const float* __restrict__ k2w, const float* __restrict__ v1w,
    const float* __restrict__ v2w,
    __half* __restrict__ hq,  __half* __restrict__ hk1, __half* __restrict__ hk2,
    __half* __restrict__ hv1, __half* __restrict__ hv2)
{
    const int wid  = threadIdx.x >> 5;
    const int lane = threadIdx.x & 31;
    const int id   = blockIdx.x * 8 + wid;   // (b*SEQ+n)*HEADS + h
    const int h    = id & 7;
    const int bn   = id >> 3;
    const int b    = bn / SEQ;
    const int n    = bn % SEQ;

    const float* base = qkv + bn * QKV_C;
    const int dst = ((b * HEADS + h) * SEQ + n) * DH;

    rms_one_h(base + h * DH,              qw,  hq  + dst, lane, QSCALE);
    rms_one_h(base + 512  + h * 128,      k1w, hk1 + dst, lane, 1.0f);
    rms_one_h(base + 512  + h * 128 + DH, k2w, hk2 + dst, lane, 1.0f);
    rms_one_h(base + 1536 + h * 128,      v1w, hv1 + dst, lane, 1.0f);
    rms_one_h(base + 1536 + h * 128 + DH, v2w, hv2 + dst, lane, 1.0f);
}

// ---------------------------------------------------------------------------
// Tensor-core attention, static-max softmax.
// Block = (split, i-tile, bh). 4 warps x 16 i-rows = 64 rows.
// ---------------------------------------------------------------------------
#define K1_STRIDE 72
#define SM_K1   (SEQ * K1_STRIDE)  // 13824 halves
#define SM_V1T  (DH * 200)         // 12800
#define SM_Q    (ITILE * DH)       //  4096
#define SM_K2   (KRANGE * DH)      //  2048
#define SM_V2   (KRANGE * DH)      //  2048
#define ATTN_SMEM_HALVES (SM_K1 + SM_V1T + SM_Q + SM_K2 + SM_V2)
#define ATTN_SMEM_BYTES  (ATTN_SMEM_HALVES * 2)

__global__ __launch_bounds__(NTHR, 3) void attn_mma(
    const __half* __restrict__ hq,  const __half* __restrict__ hk1,
    const __half* __restrict__ hk2, const __half* __restrict__ hv1,
    const __half* __restrict__ hv2,
    float* __restrict__ pacc, float* __restrict__ pl)
{
    extern __shared__ __align__(16) __half smh[];
    __half* k1s = smh;                 // [192][72]
    __half* v1t = k1s + SM_K1;         // [64][200]  (v1 transposed, padded)
    __half* qs  = v1t + SM_V1T;        // [64][64]
    __half* k2s = qs  + SM_Q;          // [KRANGE][64]
    __half* v2s = k2s + SM_K2;         // [KRANGE][64]

    const int split = blockIdx.x;
    const int i0    = blockIdx.y * ITILE;
    const int bh    = blockIdx.z;
    const int t     = threadIdx.x;
    const int kbeg  = split * KRANGE;

    const __half* k1b = hk1 + bh * SEQ * DH;
    const __half* v1b = hv1 + bh * SEQ * DH;
    const __half* k2b = hk2 + (bh * SEQ + kbeg) * DH;
    const __half* v2b = hv2 + (bh * SEQ + kbeg) * DH;
    const __half* qb  = hq  + (bh * SEQ + i0) * DH;

    for (int e = t; e < SEQ * DH; e += NTHR) {
        int j = e >> 6, d = e & 63;
        k1s[j * K1_STRIDE + d] = k1b[e];
        v1t[d * 200 + j]       = v1b[e];
    }
    for (int e = t; e < ITILE * DH; e += NTHR) qs[e] = qb[e];
    for (int e = t; e < KRANGE * DH; e += NTHR) {
        k2s[e] = k2b[e];
        v2s[e] = v2b[e];
    }
    __syncthreads();

    const int warp = t >> 5;
    const int lane = t & 31;
    const int g    = lane >> 2;      // 0..7
    const int tg   = lane & 3;       // 0..3

    const unsigned BONES = 0x3C003C00u;   // (1.0h, 1.0h)

    // q fragments (k-invariant): A[16 x 64], 4 k-chunks x 4 regs
    unsigned qa[4][4];
    {
        const __half* qr0 = qs + (warp * 16 + g) * DH;
        const __half* qr8 = qs + (warp * 16 + g + 8) * DH;
#pragma unroll
        for (int kc = 0; kc < 4; ++kc) {
            qa[kc][0] = *(const unsigned*)(qr0 + kc * 16 + 2 * tg);
            qa[kc][1] = *(const unsigned*)(qr8 + kc * 16 + 2 * tg);
            qa[kc][2] = *(const unsigned*)(qr0 + kc * 16 + 2 * tg + 8);
            qa[kc][3] = *(const unsigned*)(qr8 + kc * 16 + 2 * tg + 8);
        }
    }

    float pv[8][4];
#pragma unroll
    for (int n = 0; n < 8; ++n)
#pragma unroll
        for (int r = 0; r < 4; ++r) pv[n][r] = 0.f;
    float cl[4] = {0.f, 0.f, 0.f, 0.f};   // l accumulator (ones-column mma)

#pragma unroll 1
    for (int jc = 0; jc < NJC; ++jc) {
        // k-invariant B fragments for this j-chunk (register resident)
        unsigned bsf[4][4][2];   // S: k1^T [64d x 32j]
        unsigned bvf[2][8][2];   // PV: v1 [32j x 64d]
#pragma unroll
        for (int nt = 0; nt < 4; ++nt) {
            const __half* kr = k1s + (jc * 32 + nt * 8 + g) * K1_STRIDE + 2 * tg;
#pragma unroll
            for (int kc = 0; kc < 4; ++kc) {
                bsf[kc][nt][0] = *(const unsigned*)(kr + kc * 16);
                bsf[kc][nt][1] = *(const unsigned*)(kr + kc * 16 + 8);
            }
        }
#pragma unroll
        for (int nt = 0; nt < 8; ++nt) {
            const __half* vr = v1t + (nt * 8 + g) * 200 + jc * 32 + 2 * tg;
#pragma unroll
            for (int kc = 0; kc < 2; ++kc) {
                bvf[kc][nt][0] = *(const unsigned*)(vr + kc * 16);
                bvf[kc][nt][1] = *(const unsigned*)(vr + kc * 16 + 8);
            }
        }

#pragma unroll 1
        for (int kk = 0; kk < KRANGE; ++kk) {
            // ---- A = q o k2[k] (fp16), log2e/scale pre-folded ------------
            const __half* k2r = k2s + kk * DH;
            unsigned aa[4][4];
#pragma unroll
            for (int kc = 0; kc < 4; ++kc) {
                __half2 p0 = *(const __half2*)(k2r + kc * 16 + 2 * tg);
                __half2 p1 = *(const __half2*)(k2r + kc * 16 + 2 * tg + 8);
                aa[kc][0] = hmul2u(qa[kc][0], p0);
                aa[kc][1] = hmul2u(qa[kc][1], p0);
                aa[kc][2] = hmul2u(qa[kc][2], p1);
                aa[kc][3] = hmul2u(qa[kc][3], p1);
            }

            // ---- S[16 x 32] (log2 units) ---------------------------------
            float sc[4][4];
#pragma unroll
            for (int nt = 0; nt < 4; ++nt)
#pragma unroll
                for (int r = 0; r < 4; ++r) sc[nt][r] = 0.f;
#pragma unroll
            for (int kc = 0; kc < 4; ++kc)
#pragma unroll
                for (int nt = 0; nt < 4; ++nt)
                    mma16816(sc[nt], aa[kc][0], aa[kc][1], aa[kc][2], aa[kc][3],
                             bsf[kc][nt][0], bsf[kc][nt][1]);

            // ---- p = 2^(s - M) in fp16x2, static max (fp32 subtract) -----
            unsigned pa[2][4];
#pragma unroll
            for (int kc = 0; kc < 2; ++kc) {
                pa[kc][0] = p2exp(sc[2 * kc][0],     sc[2 * kc][1]);
                pa[kc][1] = p2exp(sc[2 * kc][2],     sc[2 * kc][3]);
                pa[kc][2] = p2exp(sc[2 * kc + 1][0], sc[2 * kc + 1][1]);
                pa[kc][3] = p2exp(sc[2 * kc + 1][2], sc[2 * kc + 1][3]);
            }

            // ---- l += P @ ones (exact fp32 row sums via mma) -------------
            mma16816(cl, pa[0][0], pa[0][1], pa[0][2], pa[0][3], BONES, BONES);
            mma16816(cl, pa[1][0], pa[1][1], pa[1][2], pa[1][3], BONES, BONES);

            // ---- PV: out += P @ (v1 o v2[k]) -----------------------------
            const __half* v2r = v2s + kk * DH;
#pragma unroll
            for (int nt = 0; nt < 8; ++nt) {
                __half2 vdd = __half2half2(v2r[nt * 8 + g]);
#pragma unroll
                for (int kc = 0; kc < 2; ++kc) {
                    unsigned b0 = hmul2u(bvf[kc][nt][0], vdd);
                    unsigned b1 = hmul2u(bvf[kc][nt][1], vdd);
                    mma16816(pv[nt], pa[kc][0], pa[kc][1], pa[kc][2], pa[kc][3],
                             b0, b1);
                }
            }
        }
    }

    // ---- write split-K partials (no max needed: static) -------------------
    const int row0 = bh * SEQ + i0 + warp * 16 + g;
    const int row1 = row0 + 8;
    const int p0   = split * BHD * SEQ + row0;
    const int p1   = split * BHD * SEQ + row1;
    if (tg == 0) {
        pl[p0] = cl[0];
        pl[p1] = cl[2];
    }
#pragma unroll
    for (int nt = 0; nt < 8; ++nt) {
        int d = nt * 8 + 2 * tg;
        *(float2*)(pacc + (size_t)p0 * DH + d) = make_float2(pv[nt][0], pv[nt][1]);
        *(float2*)(pacc + (size_t)p1 * DH + d) = make_float2(pv[nt][2], pv[nt][3]);
    }
}

// ---------------------------------------------------------------------------
// Combine KSPLIT partials (static max -> plain sums); [b,n,h*64+d].
// 256 threads, 4 rows per block.
// ---------------------------------------------------------------------------
__global__ __launch_bounds__(256) void combine_kernel(
    const float* __restrict__ pacc, const float* __restrict__ pl,
    float* __restrict__ gattn)
{
    const int row = blockIdx.x * 4 + (threadIdx.x >> 6);   // bh*SEQ + n
    const int d   = threadIdx.x & 63;

    float den = 0.f, num = 0.f;
#pragma unroll
    for (int s = 0; s < KSPLIT; ++s) {
        int idx = s * BHD * SEQ + row;
        den += pl[idx];
        num += pacc[(size_t)idx * DH + d];
    }
    float a = num / den;

    const int bh = row / SEQ, n = row % SEQ;
    const int b = bh >> 3, h = bh & 7;
    gattn[(b * SEQ + n) * DIMM + h * DH + d] = a;
}

// ---------------------------------------------------------------------------
extern "C" void kernel_launch(void* const* d_in, const int* in_sizes, int n_in,
                              void* d_out, int out_size)
{
    (void)in_sizes; (void)n_in; (void)out_size;
    const float* tokens = (const float*)d_in[0];
    const float* w_qkv  = (const float*)d_in[1];
    const float* w_out  = (const float*)d_in[2];
    const float* qw     = (const float*)d_in[3];
    const float* k1w    = (const float*)d_in[4];
    const float* k2w    = (const float*)d_in[5];
    const float* v1w    = (const float*)d_in[6];
    const float* v2w    = (const float*)d_in[7];
    float* out = (float*)d_out;

    float *qkv, *pacc, *plv, *attn;
    __half *hq, *hk1, *hk2, *hv1, *hv2;
    cudaGetSymbolAddress((void**)&qkv,  g_qkv);
    cudaGetSymbolAddress((void**)&hq,   g_hq);
    cudaGetSymbolAddress((void**)&hk1,  g_hk1);
    cudaGetSymbolAddress((void**)&hk2,  g_hk2);
    cudaGetSymbolAddress((void**)&hv1,  g_hv1);
    cudaGetSymbolAddress((void**)&hv2,  g_hv2);
    cudaGetSymbolAddress((void**)&pacc, g_pacc);
    cudaGetSymbolAddress((void**)&plv,  g_pl);
    cudaGetSymbolAddress((void**)&attn, g_attn);

    cudaFuncSetAttribute(attn_mma,
                         cudaFuncAttributeMaxDynamicSharedMemorySize,
                         ATTN_SMEM_BYTES);

    // 1) qkv = tokens @ w_qkv^T : [384,2560]  (fp16-split tensor GEMM)
    gemm_nt_tc<<<dim3(QKV_C / 64, ROWS / 64), 256>>>(tokens, w_qkv, qkv,
                                                     ROWS, QKV_C, DIMM);
    // 2) rmsnorm + split -> fp16 q*qscale, k1, k2, v1, v2 [bh, n, 64]
    rmsnorm_kernel<<<ROWS * HEADS / 8, 256>>>(qkv, qw, k1w, k2w, v1w, v2w,
                                              hq, hk1, hk2, hv1, hv2);
    // 3) tensor-core 2-simplicial attention, static-max split-K
    attn_mma<<<dim3(KSPLIT, SEQ / ITILE, BHD), NTHR, ATTN_SMEM_BYTES>>>(
        hq, hk1, hk2, hv1, hv2, pacc, plv);
    // 4) combine partials -> [b,n,h*64+d]
    combine_kernel<<<BHD * SEQ / 4, 256>>>(pacc, plv, attn);
    // 5) out = attn @ w_out^T : [384,512]
    gemm_nt_tc<<<dim3(DIMM / 64, ROWS / 64), 256>>>(attn, w_out, out,
                                                    ROWS, DIMM, DIMM);
}

// round 7
// speedup vs baseline: 14.5384x; 1.0036x over previous
#include <cuda_runtime.h>
#include <cuda_fp16.h>
#include <math_constants.h>
#include <cstdint>

// ---------------------------------------------------------------------------
// HigherOrderAttention — R7:
//   * attn: sc init = -M (bias via accumulator), k2/v2 per-thread-contiguous
//     smem layouts -> LDS.128, fewer issue slots per step
//   * GEMMs: fp16 hi/lo split precomputed (split_fp16 / combine), GEMM inner
//     loop is pure load/mma
// ---------------------------------------------------------------------------

#define TOK_B   2
#define SEQ     192
#define DIMM    512
#define HEADS   8
#define DH      64
#define BHD     (TOK_B * HEADS)        // 16
#define QKV_C   2560
#define ROWS    (TOK_B * SEQ)          // 384
#define KSPLIT  6
#define KRANGE  (SEQ / KSPLIT)         // 32
#define ITILE   64                     // i-rows per block (4 warps x 16)
#define NWARP   4
#define NTHR    (NWARP * 32)           // 128
#define NJC     (SEQ / 32)             // 6 j-chunks of 32

// static softmax max (natural units) = 5; in log2 units:
#define M_LOG2  7.2134752f             // 5 * log2(e)
#define QSCALE  0.18033688f            // 0.125 * log2(e)

// Scratch (device globals; no runtime allocation allowed)
__device__ float  g_qkv [ROWS * QKV_C];
__device__ __half g_hq  [BHD * SEQ * DH];
__device__ __half g_hk1 [BHD * SEQ * DH];
__device__ __half g_hk2 [BHD * SEQ * DH];
__device__ __half g_hv1 [BHD * SEQ * DH];
__device__ __half g_hv2 [BHD * SEQ * DH];
__device__ float  g_pacc[KSPLIT * BHD * SEQ * DH];
__device__ float  g_pl  [KSPLIT * BHD * SEQ];
// hi/lo fp16 splits for tensor-core GEMMs
__device__ __half g_th  [ROWS * DIMM],  g_tl  [ROWS * DIMM];    // tokens
__device__ __half g_wqh [QKV_C * DIMM], g_wql [QKV_C * DIMM];   // w_qkv
__device__ __half g_woh [DIMM * DIMM],  g_wol [DIMM * DIMM];    // w_out
__device__ __half g_ah  [ROWS * DIMM],  g_al  [ROWS * DIMM];    // attn

// ---------------------------------------------------------------------------
__device__ __forceinline__ void mma16816(float c[4],
                                         unsigned a0, unsigned a1,
                                         unsigned a2, unsigned a3,
                                         unsigned b0, unsigned b1)
{
    asm volatile(
        "mma.sync.aligned.m16n8k16.row.col.f32.f16.f16.f32 "
        "{%0,%1,%2,%3},{%4,%5,%6,%7},{%8,%9},{%0,%1,%2,%3};\n"
        : "+f"(c[0]), "+f"(c[1]), "+f"(c[2]), "+f"(c[3])
        : "r"(a0), "r"(a1), "r"(a2), "r"(a3), "r"(b0), "r"(b1));
}

__device__ __forceinline__ unsigned hmul2u(unsigned a, __half2 b)
{
    __half2 av = *reinterpret_cast<__half2*>(&a);
    __half2 r  = __hmul2(av, b);
    return *reinterpret_cast<unsigned*>(&r);
}

__device__ __forceinline__ __half2 u2h2(unsigned a)
{
    return *reinterpret_cast<__half2*>(&a);
}

// (a,b) already include -M via accumulator init -> cvt fp16x2 -> 2^x
__device__ __forceinline__ unsigned p2exp(float a, float b)
{
    __half2 h = __floats2half2_rn(a, b);
    unsigned x = *reinterpret_cast<unsigned*>(&h);
    unsigned r;
    asm("ex2.approx.f16x2 %0, %1;" : "=r"(r) : "r"(x));
    return r;
}

// ---------------------------------------------------------------------------
// Elementwise fp32 -> (hi, lo) fp16 split. n4 = elements/4.
// ---------------------------------------------------------------------------
__global__ __launch_bounds__(256) void split_fp16(
    const float* __restrict__ x, __half* __restrict__ hi,
    __half* __restrict__ lo, int n4)
{
    int i = blockIdx.x * 256 + threadIdx.x;
    if (i >= n4) return;
    float4 v = ((const float4*)x)[i];
    __half hx = __float2half_rn(v.x), hy = __float2half_rn(v.y);
    __half hz = __float2half_rn(v.z), hw = __float2half_rn(v.w);
    ((__half2*)hi)[2 * i]     = __halves2half2(hx, hy);
    ((__half2*)hi)[2 * i + 1] = __halves2half2(hz, hw);
    ((__half2*)lo)[2 * i]     = __halves2half2(
        __float2half_rn(v.x - __half2float(hx)),
        __float2half_rn(v.y - __half2float(hy)));
    ((__half2*)lo)[2 * i + 1] = __halves2half2(
        __float2half_rn(v.z - __half2float(hz)),
        __float2half_rn(v.w - __half2float(hw)));
}

// ---------------------------------------------------------------------------
// Tensor-core NT GEMM on pre-split hi/lo fp16 (near-fp32 accuracy):
//   C[M,N] = A[M,K] @ B[N,K]^T.  Block 64x64, 256 thr, 8 warps (4m x 2n).
// ---------------------------------------------------------------------------
__global__ __launch_bounds__(256) void gemm_nt_tch(
    const __half* __restrict__ Ah_, const __half* __restrict__ Al_,
    const __half* __restrict__ Bh_, const __half* __restrict__ Bl_,
    float* __restrict__ C, int M, int N, int K)
{
    __shared__ __half Ah[64 * 36], Al[64 * 36];
    __shared__ __half Bh[64 * 36], Bl[64 * 36];

    const int t    = threadIdx.x;
    const int m0   = blockIdx.y * 64;
    const int n0   = blockIdx.x * 64;
    const int warp = t >> 5;
    const int lane = t & 31;
    const int g    = lane >> 2;
    const int tg   = lane & 3;
    const int wm   = warp >> 1;   // 0..3
    const int wn   = warp & 1;    // 0..1

    const int lrow = t >> 2;          // 0..63
    const int lc8  = (t & 3) * 8;     // 0,8,16,24

    float c[4][4];
#pragma unroll
    for (int a = 0; a < 4; ++a)
#pragma unroll
        for (int b = 0; b < 4; ++b) c[a][b] = 0.f;

    for (int k0 = 0; k0 < K; k0 += 32) {
        __syncthreads();
        {
            size_t ga = (size_t)(m0 + lrow) * K + k0 + lc8;
            size_t gb = (size_t)(n0 + lrow) * K + k0 + lc8;
            uint4 va = *(const uint4*)(Ah_ + ga);
            uint4 vb = *(const uint4*)(Al_ + ga);
            uint4 vc = *(const uint4*)(Bh_ + gb);
            uint4 vd = *(const uint4*)(Bl_ + gb);
            __half* pa = Ah + lrow * 36 + lc8;
            __half* pb = Al + lrow * 36 + lc8;
            __half* pc = Bh + lrow * 36 + lc8;
            __half* pd = Bl + lrow * 36 + lc8;
            *(uint2*)(pa)     = make_uint2(va.x, va.y);
            *(uint2*)(pa + 4) = make_uint2(va.z, va.w);
            *(uint2*)(pb)     = make_uint2(vb.x, vb.y);
            *(uint2*)(pb + 4) = make_uint2(vb.z, vb.w);
            *(uint2*)(pc)     = make_uint2(vc.x, vc.y);
            *(uint2*)(pc + 4) = make_uint2(vc.z, vc.w);
            *(uint2*)(pd)     = make_uint2(vd.x, vd.y);
            *(uint2*)(pd + 4) = make_uint2(vd.z, vd.w);
        }
        __syncthreads();

#pragma unroll
        for (int kc = 0; kc < 2; ++kc) {
            const int ko = kc * 16 + 2 * tg;
            const __half* ar0 = Ah + (wm * 16 + g) * 36 + ko;
            const __half* ar8 = ar0 + 8 * 36;
            const __half* lr0 = Al + (wm * 16 + g) * 36 + ko;
            const __half* lr8 = lr0 + 8 * 36;

            unsigned ah0 = *(const unsigned*)(ar0);
            unsigned ah1 = *(const unsigned*)(ar8);
            unsigned ah2 = *(const unsigned*)(ar0 + 8);
            unsigned ah3 = *(const unsigned*)(ar8 + 8);
            unsigned al0 = *(const unsigned*)(lr0);
            unsigned al1 = *(const unsigned*)(lr8);
            unsigned al2 = *(const unsigned*)(lr0 + 8);
            unsigned al3 = *(const unsigned*)(lr8 + 8);

#pragma unroll
            for (int nt = 0; nt < 4; ++nt) {
                const int nrow = wn * 32 + nt * 8 + g;
                unsigned bh0 = *(const unsigned*)(Bh + nrow * 36 + ko);
                unsigned bh1 = *(const unsigned*)(Bh + nrow * 36 + ko + 8);
                unsigned bl0 = *(const unsigned*)(Bl + nrow * 36 + ko);
                unsigned bl1 = *(const unsigned*)(Bl + nrow * 36 + ko + 8);
                mma16816(c[nt], ah0, ah1, ah2, ah3, bh0, bh1);
                mma16816(c[nt], ah0, ah1, ah2, ah3, bl0, bl1);
                mma16816(c[nt], al0, al1, al2, al3, bh0, bh1);
            }
        }
    }

    const int row0 = m0 + wm * 16 + g;
    const int row1 = row0 + 8;
#pragma unroll
    for (int nt = 0; nt < 4; ++nt) {
        const int col = n0 + wn * 32 + nt * 8 + 2 * tg;
        *(float2*)(C + (size_t)row0 * N + col) = make_float2(c[nt][0], c[nt][1]);
        *(float2*)(C + (size_t)row1 * N + col) = make_float2(c[nt][2], c[nt][3]);
    }
}

// ---------------------------------------------------------------------------
// RMSNorm + head split; emits fp16 (q pre-scaled by 0.125*log2e).
// ---------------------------------------------------------------------------
__device__ __forceinline__ void rms_one_h(const float* __restrict__ x,
                                          const float* __restrict__ w,
                                          __half* __restrict__ y, int lane,
                                          float scale)
{
    float x0 = x[lane];
    float x1 = x[lane + 32];
    float ss = x0 * x0 + x1 * x1;
#pragma unroll
    for (int o = 16; o >= 1; o >>= 1)
        ss += __shfl_xor_sync(0xffffffffu, ss, o);
    float inv = rsqrtf(ss * (1.0f / 64.0f) + 1.1920929e-07f) * scale;
    y[lane]      = __float2half(x0 * inv * w[lane]);
    y[lane + 32] = __float2half(x1 * inv * w[lane + 32]);
}

__global__ __launch_bounds__(256) void rmsnorm_kernel(
    const float* __restrict__ qkv,
    const float* __restrict__ qw,  const float* __restrict__ k1w,
    const float* __restrict__ k2w, const float* __restrict__ v1w,
    const float* __restrict__ v2w,
    __half* __restrict__ hq,  __half* __restrict__ hk1, __half* __restrict__ hk2,
    __half* __restrict__ hv1, __half* __restrict__ hv2)
{
    const int wid  = threadIdx.x >> 5;
    const int lane = threadIdx.x & 31;
    const int id   = blockIdx.x * 8 + wid;   // (b*SEQ+n)*HEADS + h
    const int h    = id & 7;
    const int bn   = id >> 3;
    const int b    = bn / SEQ;
    const int n    = bn % SEQ;

    const float* base = qkv + bn * QKV_C;
    const int dst = ((b * HEADS + h) * SEQ + n) * DH;

    rms_one_h(base + h * DH,              qw,  hq  + dst, lane, QSCALE);
    rms_one_h(base + 512  + h * 128,      k1w, hk1 + dst, lane, 1.0f);
    rms_one_h(base + 512  + h * 128 + DH, k2w, hk2 + dst, lane, 1.0f);
    rms_one_h(base + 1536 + h * 128,      v1w, hv1 + dst, lane, 1.0f);
    rms_one_h(base + 1536 + h * 128 + DH, v2w, hv2 + dst, lane, 1.0f);
}

// ---------------------------------------------------------------------------
// Tensor-core attention, static-max softmax.
// Block = (split, i-tile, bh). 4 warps x 16 i-rows = 64 rows.
// k2 stored per-(k,tg) contiguous (8 half2); v2 per-(k,g) contiguous (8 half).
// ---------------------------------------------------------------------------
#define K1_STRIDE 72
#define SM_K1   (SEQ * K1_STRIDE)  // 13824 halves
#define SM_V1T  (DH * 200)         // 12800
#define SM_Q    (ITILE * DH)       //  4096
#define SM_K2   (KRANGE * DH)      //  2048 (as half2: KRANGE*32)
#define SM_V2   (KRANGE * DH)      //  2048
#define ATTN_SMEM_HALVES (SM_K1 + SM_V1T + SM_Q + SM_K2 + SM_V2)
#define ATTN_SMEM_BYTES  (ATTN_SMEM_HALVES * 2)

__global__ __launch_bounds__(NTHR, 3) void attn_mma(
    const __half* __restrict__ hq,  const __half* __restrict__ hk1,
    const __half* __restrict__ hk2, const __half* __restrict__ hv1,
    const __half* __restrict__ hv2,
    float* __restrict__ pacc, float* __restrict__ pl)
{
    extern __shared__ __align__(16) __half smh[];
    __half*  k1s  = smh;                      // [192][72]
    __half*  v1t  = k1s + SM_K1;              // [64][200]
    __half*  qs   = v1t + SM_V1T;             // [64][64]
    __half2* k2t2 = (__half2*)(qs + SM_Q);    // [KRANGE][4 tg][8]
    __half*  v2t  = qs + SM_Q + SM_K2;        // [KRANGE][8 g][8 nt]

    const int split = blockIdx.x;
    const int i0    = blockIdx.y * ITILE;
    const int bh    = blockIdx.z;
    const int t     = threadIdx.x;
    const int kbeg  = split * KRANGE;

    const __half* k1b = hk1 + bh * SEQ * DH;
    const __half* v1b = hv1 + bh * SEQ * DH;
    const __half* k2b = hk2 + (bh * SEQ + kbeg) * DH;
    const __half* v2b = hv2 + (bh * SEQ + kbeg) * DH;
    const __half* qb  = hq  + (bh * SEQ + i0) * DH;

    for (int e = t; e < SEQ * DH; e += NTHR) {
        int j = e >> 6, d = e & 63;
        k1s[j * K1_STRIDE + d] = k1b[e];
        v1t[d * 200 + j]       = v1b[e];
    }
    for (int e = t; e < ITILE * DH; e += NTHR) qs[e] = qb[e];
    // k2 relayout: entry e -> (kk, tg, s) ; s = kc*2+h ; col = kc*16+h*8+tg*2
    for (int e = t; e < KRANGE * 32; e += NTHR) {
        int kk = e >> 5, r = e & 31;
        int tg_ = r >> 3, s = r & 7;
        int col = (s >> 1) * 16 + (s & 1) * 8 + tg_ * 2;
        k2t2[e] = *(const __half2*)(k2b + kk * DH + col);
    }
    // v2 relayout: entry e -> (kk, g, nt) ; col = nt*8+g
    for (int e = t; e < KRANGE * 64; e += NTHR) {
        int kk = e >> 6, r = e & 63;
        int g_ = r >> 3, nt = r & 7;
        v2t[e] = v2b[kk * DH + nt * 8 + g_];
    }
    __syncthreads();

    const int warp = t >> 5;
    const int lane = t & 31;
    const int g    = lane >> 2;      // 0..7
    const int tg   = lane & 3;       // 0..3

    const unsigned BONES = 0x3C003C00u;   // (1.0h, 1.0h)

    // q fragments (k-invariant): A[16 x 64], 4 k-chunks x 4 regs
    unsigned qa[4][4];
    {
        const __half* qr0 = qs + (warp * 16 + g) * DH;
        const __half* qr8 = qs + (warp * 16 + g + 8) * DH;
#pragma unroll
        for (int kc = 0; kc < 4; ++kc) {
            qa[kc][0] = *(const unsigned*)(qr0 + kc * 16 + 2 * tg);
            qa[kc][1] = *(const unsigned*)(qr8 + kc * 16 + 2 * tg);
            qa[kc][2] = *(const unsigned*)(qr0 + kc * 16 + 2 * tg + 8);
            qa[kc][3] = *(const unsigned*)(qr8 + kc * 16 + 2 * tg + 8);
        }
    }

    float pv[8][4];
#pragma unroll
    for (int n = 0; n < 8; ++n)
#pragma unroll
        for (int r = 0; r < 4; ++r) pv[n][r] = 0.f;
    float cl[4] = {0.f, 0.f, 0.f, 0.f};

#pragma unroll 1
    for (int jc = 0; jc < NJC; ++jc) {
        unsigned bsf[4][4][2];   // S: k1^T [64d x 32j]
        unsigned bvf[2][8][2];   // PV: v1 [32j x 64d]
#pragma unroll
        for (int nt = 0; nt < 4; ++nt) {
            const __half* kr = k1s + (jc * 32 + nt * 8 + g) * K1_STRIDE + 2 * tg;
#pragma unroll
            for (int kc = 0; kc < 4; ++kc) {
                bsf[kc][nt][0] = *(const unsigned*)(kr + kc * 16);
                bsf[kc][nt][1] = *(const unsigned*)(kr + kc * 16 + 8);
            }
        }
#pragma unroll
        for (int nt = 0; nt < 8; ++nt) {
            const __half* vr = v1t + (nt * 8 + g) * 200 + jc * 32 + 2 * tg;
#pragma unroll
            for (int kc = 0; kc < 2; ++kc) {
                bvf[kc][nt][0] = *(const unsigned*)(vr + kc * 16);
                bvf[kc][nt][1] = *(const unsigned*)(vr + kc * 16 + 8);
            }
        }

#pragma unroll 1
        for (int kk = 0; kk < KRANGE; ++kk) {
            // ---- k2 for this step: 8 half2, two LDS.128 ------------------
            const __half2* k2p = k2t2 + (size_t)(kk * 4 + tg) * 8;
            uint4 kr0 = *(const uint4*)(k2p);
            uint4 kr1 = *(const uint4*)(k2p + 4);
            const unsigned kh[8] = {kr0.x, kr0.y, kr0.z, kr0.w,
                                    kr1.x, kr1.y, kr1.z, kr1.w};

            // ---- A = q o k2[k] (fp16) ------------------------------------
            unsigned aa[4][4];
#pragma unroll
            for (int kc = 0; kc < 4; ++kc) {
                __half2 p0 = u2h2(kh[kc * 2]);
                __half2 p1 = u2h2(kh[kc * 2 + 1]);
                aa[kc][0] = hmul2u(qa[kc][0], p0);
                aa[kc][1] = hmul2u(qa[kc][1], p0);
                aa[kc][2] = hmul2u(qa[kc][2], p1);
                aa[kc][3] = hmul2u(qa[kc][3], p1);
            }

            // ---- S[16 x 32] (log2 units), accumulator pre-biased by -M ---
            float sc[4][4];
#pragma unroll
            for (int nt = 0; nt < 4; ++nt)
#pragma unroll
                for (int r = 0; r < 4; ++r) sc[nt][r] = -M_LOG2;
#pragma unroll
            for (int kc = 0; kc < 4; ++kc)
#pragma unroll
                for (int nt = 0; nt < 4; ++nt)
                    mma16816(sc[nt], aa[kc][0], aa[kc][1], aa[kc][2], aa[kc][3],
                             bsf[kc][nt][0], bsf[kc][nt][1]);

            // ---- p = 2^(s - M) in fp16x2 ---------------------------------
            unsigned pa[2][4];
#pragma unroll
            for (int kc = 0; kc < 2; ++kc) {
                pa[kc][0] = p2exp(sc[2 * kc][0],     sc[2 * kc][1]);
                pa[kc][1] = p2exp(sc[2 * kc][2],     sc[2 * kc][3]);
                pa[kc][2] = p2exp(sc[2 * kc + 1][0], sc[2 * kc + 1][1]);
                pa[kc][3] = p2exp(sc[2 * kc + 1][2], sc[2 * kc + 1][3]);
            }

            // ---- l += P @ ones -------------------------------------------
            mma16816(cl, pa[0][0], pa[0][1], pa[0][2], pa[0][3], BONES, BONES);
            mma16816(cl, pa[1][0], pa[1][1], pa[1][2], pa[1][3], BONES, BONES);

            // ---- v2 for this step: 8 halves, one LDS.128 -----------------
            const __half* v2p = v2t + (size_t)(kk * 8 + g) * 8;
            uint4 vraw = *(const uint4*)(v2p);
            const unsigned vhp[4] = {vraw.x, vraw.y, vraw.z, vraw.w};

            // ---- PV: out += P @ (v1 o v2[k]) -----------------------------
#pragma unroll
            for (int nt = 0; nt < 8; ++nt) {
                __half2 pair = u2h2(vhp[nt >> 1]);
                __half2 vdd  = (nt & 1) ? __high2half2(pair) : __low2half2(pair);
#pragma unroll
                for (int kc = 0; kc < 2; ++kc) {
                    unsigned b0 = hmul2u(bvf[kc][nt][0], vdd);
                    unsigned b1 = hmul2u(bvf[kc][nt][1], vdd);
                    mma16816(pv[nt], pa[kc][0], pa[kc][1], pa[kc][2], pa[kc][3],
                             b0, b1);
                }
            }
        }
    }

    // ---- write split-K partials -------------------------------------------
    const int row0 = bh * SEQ + i0 + warp * 16 + g;
    const int row1 = row0 + 8;
    const int p0   = split * BHD * SEQ + row0;
    const int p1   = split * BHD * SEQ + row1;
    if (tg == 0) {
        pl[p0] = cl[0];
        pl[p1] = cl[2];
    }
#pragma unroll
    for (int nt = 0; nt < 8; ++nt) {
        int d = nt * 8 + 2 * tg;
        *(float2*)(pacc + (size_t)p0 * DH + d) = make_float2(pv[nt][0], pv[nt][1]);
        *(float2*)(pacc + (size_t)p1 * DH + d) = make_float2(pv[nt][2], pv[nt][3]);
    }
}

// ---------------------------------------------------------------------------
// Combine KSPLIT partials; write attn as fp16 hi/lo at [b,n,h*64+d].
// 256 threads, 4 rows per block.
// ---------------------------------------------------------------------------
__global__ __launch_bounds__(256) void combine_kernel(
    const float* __restrict__ pacc, const float* __restrict__ pl,
    __half* __restrict__ ahi, __half* __restrict__ alo)
{
    const int row = blockIdx.x * 4 + (threadIdx.x >> 6);   // bh*SEQ + n
    const int d   = threadIdx.x & 63;

    float den = 0.f, num = 0.f;
#pragma unroll
    for (int s = 0; s < KSPLIT; ++s) {
        int idx = s * BHD * SEQ + row;
        den += pl[idx];
        num += pacc[(size_t)idx * DH + d];
    }
    float a = num / den;

    const int bh = row / SEQ, n = row % SEQ;
    const int b = bh >> 3, h = bh & 7;
    const int o = (b * SEQ + n) * DIMM + h * DH + d;
    __half hi = __float2half_rn(a);
    ahi[o] = hi;
    alo[o] = __float2half_rn(a - __half2float(hi));
}

// ---------------------------------------------------------------------------
extern "C" void kernel_launch(void* const* d_in, const int* in_sizes, int n_in,
                              void* d_out, int out_size)
{
    (void)in_sizes; (void)n_in; (void)out_size;
    const float* tokens = (const float*)d_in[0];
    const float* w_qkv  = (const float*)d_in[1];
    const float* w_out  = (const float*)d_in[2];
    const float* qw     = (const float*)d_in[3];
    const float* k1w    = (const float*)d_in[4];
    const float* k2w    = (const float*)d_in[5];
    const float* v1w    = (const float*)d_in[6];
    const float* v2w    = (const float*)d_in[7];
    float* out = (float*)d_out;

    float *qkv, *pacc, *plv;
    __half *hq, *hk1, *hk2, *hv1, *hv2;
    __half *th, *tl, *wqh, *wql, *woh, *wol, *ah, *al;
    cudaGetSymbolAddress((void**)&qkv,  g_qkv);
    cudaGetSymbolAddress((void**)&hq,   g_hq);
    cudaGetSymbolAddress((void**)&hk1,  g_hk1);
    cudaGetSymbolAddress((void**)&hk2,  g_hk2);
    cudaGetSymbolAddress((void**)&hv1,  g_hv1);
    cudaGetSymbolAddress((void**)&hv2,  g_hv2);
    cudaGetSymbolAddress((void**)&pacc, g_pacc);
    cudaGetSymbolAddress((void**)&plv,  g_pl);
    cudaGetSymbolAddress((void**)&th,   g_th);
    cudaGetSymbolAddress((void**)&tl,   g_tl);
    cudaGetSymbolAddress((void**)&wqh,  g_wqh);
    cudaGetSymbolAddress((void**)&wql,  g_wql);
    cudaGetSymbolAddress((void**)&woh,  g_woh);
    cudaGetSymbolAddress((void**)&wol,  g_wol);
    cudaGetSymbolAddress((void**)&ah,   g_ah);
    cudaGetSymbolAddress((void**)&al,   g_al);

    cudaFuncSetAttribute(attn_mma,
                         cudaFuncAttributeMaxDynamicSharedMemorySize,
                         ATTN_SMEM_BYTES);

    // 0) hi/lo splits of GEMM operands
    split_fp16<<<(ROWS * DIMM / 4 + 255) / 256, 256>>>(tokens, th, tl,
                                                       ROWS * DIMM / 4);
    split_fp16<<<(QKV_C * DIMM / 4 + 255) / 256, 256>>>(w_qkv, wqh, wql,
                                                        QKV_C * DIMM / 4);
    split_fp16<<<(DIMM * DIMM / 4 + 255) / 256, 256>>>(w_out, woh, wol,
                                                       DIMM * DIMM / 4);
    // 1) qkv = tokens @ w_qkv^T : [384,2560]
    gemm_nt_tch<<<dim3(QKV_C / 64, ROWS / 64), 256>>>(th, tl, wqh, wql, qkv,
                                                      ROWS, QKV_C, DIMM);
    // 2) rmsnorm + split -> fp16 q*qscale, k1, k2, v1, v2 [bh, n, 64]
    rmsnorm_kernel<<<ROWS * HEADS / 8, 256>>>(qkv, qw, k1w, k2w, v1w, v2w,
                                              hq, hk1, hk2, hv1, hv2);
    // 3) tensor-core 2-simplicial attention, static-max split-K
    attn_mma<<<dim3(KSPLIT, SEQ / ITILE, BHD), NTHR, ATTN_SMEM_BYTES>>>(
        hq, hk1, hk2, hv1, hv2, pacc, plv);
    // 4) combine partials -> attn hi/lo [b,n,h*64+d]
    combine_kernel<<<BHD * SEQ / 4, 256>>>(pacc, plv, ah, al);
    // 5) out = attn @ w_out^T : [384,512]
    gemm_nt_tch<<<dim3(DIMM / 64, ROWS / 64), 256>>>(ah, al, woh, wol, out,
                                                     ROWS, DIMM, DIMM);
}

// round 8
// speedup vs baseline: 16.4691x; 1.1328x over previous
#include <cuda_runtime.h>
#include <cuda_fp16.h>
#include <math_constants.h>
#include <cstdint>

// ---------------------------------------------------------------------------
// HigherOrderAttention — R8:
//   * GEMM: ldmatrix.x4 fragment loads (64 LDS.32 -> 12 LDSM per warp-kstep)
//     + register/smem double-buffered mainloop (1 sync/iter)
//   * fused split3_fp16 (one launch for tokens/w_qkv/w_out hi-lo split)
//   * attn / rmsnorm / combine unchanged from R7 (validated)
// ---------------------------------------------------------------------------

#define TOK_B   2
#define SEQ     192
#define DIMM    512
#define HEADS   8
#define DH      64
#define BHD     (TOK_B * HEADS)        // 16
#define QKV_C   2560
#define ROWS    (TOK_B * SEQ)          // 384
#define KSPLIT  6
#define KRANGE  (SEQ / KSPLIT)         // 32
#define ITILE   64
#define NWARP   4
#define NTHR    (NWARP * 32)           // 128
#define NJC     (SEQ / 32)             // 6

#define M_LOG2  7.2134752f             // 5 * log2(e)
#define QSCALE  0.18033688f            // 0.125 * log2(e)

// Scratch (device globals)
__device__ float  g_qkv [ROWS * QKV_C];
__device__ __half g_hq  [BHD * SEQ * DH];
__device__ __half g_hk1 [BHD * SEQ * DH];
__device__ __half g_hk2 [BHD * SEQ * DH];
__device__ __half g_hv1 [BHD * SEQ * DH];
__device__ __half g_hv2 [BHD * SEQ * DH];
__device__ float  g_pacc[KSPLIT * BHD * SEQ * DH];
__device__ float  g_pl  [KSPLIT * BHD * SEQ];
__device__ __half g_th  [ROWS * DIMM],  g_tl  [ROWS * DIMM];
__device__ __half g_wqh [QKV_C * DIMM], g_wql [QKV_C * DIMM];
__device__ __half g_woh [DIMM * DIMM],  g_wol [DIMM * DIMM];
__device__ __half g_ah  [ROWS * DIMM],  g_al  [ROWS * DIMM];

// ---------------------------------------------------------------------------
__device__ __forceinline__ void mma16816(float c[4],
                                         unsigned a0, unsigned a1,
                                         unsigned a2, unsigned a3,
                                         unsigned b0, unsigned b1)
{
    asm volatile(
        "mma.sync.aligned.m16n8k16.row.col.f32.f16.f16.f32 "
        "{%0,%1,%2,%3},{%4,%5,%6,%7},{%8,%9},{%0,%1,%2,%3};\n"
        : "+f"(c[0]), "+f"(c[1]), "+f"(c[2]), "+f"(c[3])
        : "r"(a0), "r"(a1), "r"(a2), "r"(a3), "r"(b0), "r"(b1));
}

__device__ __forceinline__ void ldsm_x4(unsigned r[4], const __half* p)
{
    unsigned sa = (unsigned)__cvta_generic_to_shared(p);
    asm volatile("ldmatrix.sync.aligned.m8n8.x4.shared.b16 {%0,%1,%2,%3}, [%4];"
                 : "=r"(r[0]), "=r"(r[1]), "=r"(r[2]), "=r"(r[3]) : "r"(sa));
}

__device__ __forceinline__ unsigned hmul2u(unsigned a, __half2 b)
{
    __half2 av = *reinterpret_cast<__half2*>(&a);
    __half2 r  = __hmul2(av, b);
    return *reinterpret_cast<unsigned*>(&r);
}

__device__ __forceinline__ __half2 u2h2(unsigned a)
{
    return *reinterpret_cast<__half2*>(&a);
}

__device__ __forceinline__ unsigned p2exp(float a, float b)
{
    __half2 h = __floats2half2_rn(a, b);
    unsigned x = *reinterpret_cast<unsigned*>(&h);
    unsigned r;
    asm("ex2.approx.f16x2 %0, %1;" : "=r"(r) : "r"(x));
    return r;
}

// ---------------------------------------------------------------------------
// Fused fp32 -> (hi,lo) fp16 split for 3 arrays. i indexes float4 quads.
// ---------------------------------------------------------------------------
__device__ __forceinline__ void split_quad(const float* __restrict__ x,
                                           __half* __restrict__ hi,
                                           __half* __restrict__ lo, int i)
{
    float4 v = ((const float4*)x)[i];
    __half hx = __float2half_rn(v.x), hy = __float2half_rn(v.y);
    __half hz = __float2half_rn(v.z), hw = __float2half_rn(v.w);
    ((__half2*)hi)[2 * i]     = __halves2half2(hx, hy);
    ((__half2*)hi)[2 * i + 1] = __halves2half2(hz, hw);
    ((__half2*)lo)[2 * i]     = __halves2half2(
        __float2half_rn(v.x - __half2float(hx)),
        __float2half_rn(v.y - __half2float(hy)));
    ((__half2*)lo)[2 * i + 1] = __halves2half2(
        __float2half_rn(v.z - __half2float(hz)),
        __float2half_rn(v.w - __half2float(hw)));
}

#define N0Q (ROWS * DIMM / 4)
#define N1Q (QKV_C * DIMM / 4)
#define N2Q (DIMM * DIMM / 4)

__global__ __launch_bounds__(256) void split3_fp16(
    const float* __restrict__ x0, __half* __restrict__ h0, __half* __restrict__ l0,
    const float* __restrict__ x1, __half* __restrict__ h1, __half* __restrict__ l1,
    const float* __restrict__ x2, __half* __restrict__ h2, __half* __restrict__ l2)
{
    int i = blockIdx.x * 256 + threadIdx.x;
    if (i < N0Q) {
        split_quad(x0, h0, l0, i);
    } else if (i < N0Q + N1Q) {
        split_quad(x1, h1, l1, i - N0Q);
    } else if (i < N0Q + N1Q + N2Q) {
        split_quad(x2, h2, l2, i - N0Q - N1Q);
    }
}

// ---------------------------------------------------------------------------
// Tensor-core NT GEMM on pre-split hi/lo fp16, ldmatrix + double buffer.
//   C[M,N] = A[M,K] @ B[N,K]^T.  Block 64x64, 256 thr, 8 warps (4m x 2n).
//   K must be a multiple of 32.
// ---------------------------------------------------------------------------
#define GS 40   // smem row stride in halves (80B, 16B-aligned for ldmatrix)

__global__ __launch_bounds__(256) void gemm_nt_tch(
    const __half* __restrict__ Ah_, const __half* __restrict__ Al_,
    const __half* __restrict__ Bh_, const __half* __restrict__ Bl_,
    float* __restrict__ C, int M, int N, int K)
{
    __shared__ __half sm[2][4][64 * GS];   // [buf][Ah,Al,Bh,Bl]

    const int t    = threadIdx.x;
    const int m0   = blockIdx.y * 64;
    const int n0   = blockIdx.x * 64;
    const int warp = t >> 5;
    const int lane = t & 31;
    const int g    = lane >> 2;
    const int tg   = lane & 3;
    const int wm   = warp >> 1;   // 0..3
    const int wn   = warp & 1;    // 0..1

    const int lrow = t >> 2;          // 0..63
    const int lc8  = (t & 3) * 8;     // 0,8,16,24

    // ldmatrix source offsets (halves)
    const int a_off = (wm * 16 + (lane & 15)) * GS + 8 * (lane >> 4);
    const int b_row = wn * 32 + (lane & 7) + ((lane >> 4) & 1) * 8;
    const int b_c8  = ((lane >> 3) & 1) * 8;

    float c[4][4];
#pragma unroll
    for (int a = 0; a < 4; ++a)
#pragma unroll
        for (int b = 0; b < 4; ++b) c[a][b] = 0.f;

    const int NIT = K >> 5;
    uint4 ra, rb, rc, rd;

    // prologue: load k-tile 0, stage into buf 0
    {
        size_t ga = (size_t)(m0 + lrow) * K + lc8;
        size_t gb = (size_t)(n0 + lrow) * K + lc8;
        ra = *(const uint4*)(Ah_ + ga);
        rb = *(const uint4*)(Al_ + ga);
        rc = *(const uint4*)(Bh_ + gb);
        rd = *(const uint4*)(Bl_ + gb);
        __half* p = &sm[0][0][lrow * GS + lc8];
        *(uint4*)(p)               = ra;
        *(uint4*)(p + 64 * GS)     = rb;
        *(uint4*)(p + 2 * 64 * GS) = rc;
        *(uint4*)(p + 3 * 64 * GS) = rd;
    }
    __syncthreads();

#pragma unroll 1
    for (int it = 0; it < NIT; ++it) {
        const int cur = it & 1;

        if (it + 1 < NIT) {
            size_t ga = (size_t)(m0 + lrow) * K + (it + 1) * 32 + lc8;
            size_t gb = (size_t)(n0 + lrow) * K + (it + 1) * 32 + lc8;
            ra = *(const uint4*)(Ah_ + ga);
            rb = *(const uint4*)(Al_ + ga);
            rc = *(const uint4*)(Bh_ + gb);
            rd = *(const uint4*)(Bl_ + gb);
        }

        const __half* Ahs = sm[cur][0];
        const __half* Als = sm[cur][1];
        const __half* Bhs = sm[cur][2];
        const __half* Bls = sm[cur][3];

#pragma unroll
        for (int kc = 0; kc < 2; ++kc) {
            const int ko = kc * 16;
            unsigned ah[4], al[4];
            ldsm_x4(ah, Ahs + a_off + ko);
            ldsm_x4(al, Als + a_off + ko);
#pragma unroll
            for (int p = 0; p < 2; ++p) {
                unsigned bh[4], bl[4];
                const int bo = (b_row + p * 16) * GS + ko + b_c8;
                ldsm_x4(bh, Bhs + bo);
                ldsm_x4(bl, Bls + bo);
                // nt = 2p   : frags (bh[0],bh[1])
                mma16816(c[2 * p],     ah[0], ah[1], ah[2], ah[3], bh[0], bh[1]);
                mma16816(c[2 * p],     ah[0], ah[1], ah[2], ah[3], bl[0], bl[1]);
                mma16816(c[2 * p],     al[0], al[1], al[2], al[3], bh[0], bh[1]);
                // nt = 2p+1 : frags (bh[2],bh[3])
                mma16816(c[2 * p + 1], ah[0], ah[1], ah[2], ah[3], bh[2], bh[3]);
                mma16816(c[2 * p + 1], ah[0], ah[1], ah[2], ah[3], bl[2], bl[3]);
                mma16816(c[2 * p + 1], al[0], al[1], al[2], al[3], bh[2], bh[3]);
            }
        }

        if (it + 1 < NIT) {
            __half* p = &sm[cur ^ 1][0][lrow * GS + lc8];
            *(uint4*)(p)               = ra;
            *(uint4*)(p + 64 * GS)     = rb;
            *(uint4*)(p + 2 * 64 * GS) = rc;
            *(uint4*)(p + 3 * 64 * GS) = rd;
            __syncthreads();
        }
    }

    const int row0 = m0 + wm * 16 + g;
    const int row1 = row0 + 8;
#pragma unroll
    for (int nt = 0; nt < 4; ++nt) {
        const int col = n0 + wn * 32 + nt * 8 + 2 * tg;
        *(float2*)(C + (size_t)row0 * N + col) = make_float2(c[nt][0], c[nt][1]);
        *(float2*)(C + (size_t)row1 * N + col) = make_float2(c[nt][2], c[nt][3]);
    }
}

// ---------------------------------------------------------------------------
// RMSNorm + head split; emits fp16 (q pre-scaled by 0.125*log2e).
// ---------------------------------------------------------------------------
__device__ __forceinline__ void rms_one_h(const float* __restrict__ x,
                                          const float* __restrict__ w,
                                          __half* __restrict__ y, int lane,
                                          float scale)
{
    float x0 = x[lane];
    float x1 = x[lane + 32];
    float ss = x0 * x0 + x1 * x1;
#pragma unroll
    for (int o = 16; o >= 1; o >>= 1)
        ss += __shfl_xor_sync(0xffffffffu, ss, o);
    float inv = rsqrtf(ss * (1.0f / 64.0f) + 1.1920929e-07f) * scale;
    y[lane]      = __float2half(x0 * inv * w[lane]);
    y[lane + 32] = __float2half(x1 * inv * w[lane + 32]);
}

__global__ __launch_bounds__(256) void rmsnorm_kernel(
    const float* __restrict__ qkv,
    const float* __restrict__ qw,  const float* __restrict__ k1w,
    const float* __restrict__ k2w, const float* __restrict__ v1w,
    const float* __restrict__ v2w,
    __half* __restrict__ hq,  __half* __restrict__ hk1, __half* __restrict__ hk2,
    __half* __restrict__ hv1, __half* __restrict__ hv2)
{
    const int wid  = threadIdx.x >> 5;
    const int lane = threadIdx.x & 31;
    const int id   = blockIdx.x * 8 + wid;
    const int h    = id & 7;
    const int bn   = id >> 3;
    const int b    = bn / SEQ;
    const int n    = bn % SEQ;

    const float* base = qkv + bn * QKV_C;
    const int dst = ((b * HEADS + h) * SEQ + n) * DH;

    rms_one_h(base + h * DH,              qw,  hq  + dst, lane, QSCALE);
    rms_one_h(base + 512  + h * 128,      k1w, hk1 + dst, lane, 1.0f);
    rms_one_h(base + 512  + h * 128 + DH, k2w, hk2 + dst, lane, 1.0f);
    rms_one_h(base + 1536 + h * 128,      v1w, hv1 + dst, lane, 1.0f);
    rms_one_h(base + 1536 + h * 128 + DH, v2w, hv2 + dst, lane, 1.0f);
}

// ---------------------------------------------------------------------------
// Tensor-core attention, static-max softmax (unchanged from R7).
// ---------------------------------------------------------------------------
#define K1_STRIDE 72
#define SM_K1   (SEQ * K1_STRIDE)
#define SM_V1T  (DH * 200)
#define SM_Q    (ITILE * DH)
#define SM_K2   (KRANGE * DH)
#define SM_V2   (KRANGE * DH)
#define ATTN_SMEM_HALVES (SM_K1 + SM_V1T + SM_Q + SM_K2 + SM_V2)
#define ATTN_SMEM_BYTES  (ATTN_SMEM_HALVES * 2)

__global__ __launch_bounds__(NTHR, 3) void attn_mma(
    const __half* __restrict__ hq,  const __half* __restrict__ hk1,
    const __half* __restrict__ hk2, const __half* __restrict__ hv1,
    const __half* __restrict__ hv2,
    float* __restrict__ pacc, float* __restrict__ pl)
{
    extern __shared__ __align__(16) __half smh[];
    __half*  k1s  = smh;
    __half*  v1t  = k1s + SM_K1;
    __half*  qs   = v1t + SM_V1T;
    __half2* k2t2 = (__half2*)(qs + SM_Q);
    __half*  v2t  = qs + SM_Q + SM_K2;

    const int split = blockIdx.x;
    const int i0    = blockIdx.y * ITILE;
    const int bh    = blockIdx.z;
    const int t     = threadIdx.x;
    const int kbeg  = split * KRANGE;

    const __half* k1b = hk1 + bh * SEQ * DH;
    const __half* v1b = hv1 + bh * SEQ * DH;
    const __half* k2b = hk2 + (bh * SEQ + kbeg) * DH;
    const __half* v2b = hv2 + (bh * SEQ + kbeg) * DH;
    const __half* qb  = hq  + (bh * SEQ + i0) * DH;

    for (int e = t; e < SEQ * DH; e += NTHR) {
        int j = e >> 6, d = e & 63;
        k1s[j * K1_STRIDE + d] = k1b[e];
        v1t[d * 200 + j]       = v1b[e];
    }
    for (int e = t; e < ITILE * DH; e += NTHR) qs[e] = qb[e];
    for (int e = t; e < KRANGE * 32; e += NTHR) {
        int kk = e >> 5, r = e & 31;
        int tg_ = r >> 3, s = r & 7;
        int col = (s >> 1) * 16 + (s & 1) * 8 + tg_ * 2;
        k2t2[e] = *(const __half2*)(k2b + kk * DH + col);
    }
    for (int e = t; e < KRANGE * 64; e += NTHR) {
        int kk = e >> 6, r = e & 63;
        int g_ = r >> 3, nt = r & 7;
        v2t[e] = v2b[kk * DH + nt * 8 + g_];
    }
    __syncthreads();

    const int warp = t >> 5;
    const int lane = t & 31;
    const int g    = lane >> 2;
    const int tg   = lane & 3;

    const unsigned BONES = 0x3C003C00u;

    unsigned qa[4][4];
    {
        const __half* qr0 = qs + (warp * 16 + g) * DH;
        const __half* qr8 = qs + (warp * 16 + g + 8) * DH;
#pragma unroll
        for (int kc = 0; kc < 4; ++kc) {
            qa[kc][0] = *(const unsigned*)(qr0 + kc * 16 + 2 * tg);
            qa[kc][1] = *(const unsigned*)(qr8 + kc * 16 + 2 * tg);
            qa[kc][2] = *(const unsigned*)(qr0 + kc * 16 + 2 * tg + 8);
            qa[kc][3] = *(const unsigned*)(qr8 + kc * 16 + 2 * tg + 8);
        }
    }

    float pv[8][4];
#pragma unroll
    for (int n = 0; n < 8; ++n)
#pragma unroll
        for (int r = 0; r < 4; ++r) pv[n][r] = 0.f;
    float cl[4] = {0.f, 0.f, 0.f, 0.f};

#pragma unroll 1
    for (int jc = 0; jc < NJC; ++jc) {
        unsigned bsf[4][4][2];
        unsigned bvf[2][8][2];
#pragma unroll
        for (int nt = 0; nt < 4; ++nt) {
            const __half* kr = k1s + (jc * 32 + nt * 8 + g) * K1_STRIDE + 2 * tg;
#pragma unroll
            for (int kc = 0; kc < 4; ++kc) {
                bsf[kc][nt][0] = *(const unsigned*)(kr + kc * 16);
                bsf[kc][nt][1] = *(const unsigned*)(kr + kc * 16 + 8);
            }
        }
#pragma unroll
        for (int nt = 0; nt < 8; ++nt) {
            const __half* vr = v1t + (nt * 8 + g) * 200 + jc * 32 + 2 * tg;
#pragma unroll
            for (int kc = 0; kc < 2; ++kc) {
                bvf[kc][nt][0] = *(const unsigned*)(vr + kc * 16);
                bvf[kc][nt][1] = *(const unsigned*)(vr + kc * 16 + 8);
            }
        }

#pragma unroll 1
        for (int kk = 0; kk < KRANGE; ++kk) {
            const __half2* k2p = k2t2 + (size_t)(kk * 4 + tg) * 8;
            uint4 kr0 = *(const uint4*)(k2p);
            uint4 kr1 = *(const uint4*)(k2p + 4);
            const unsigned kh[8] = {kr0.x, kr0.y, kr0.z, kr0.w,
                                    kr1.x, kr1.y, kr1.z, kr1.w};

            unsigned aa[4][4];
#pragma unroll
            for (int kc = 0; kc < 4; ++kc) {
                __half2 p0 = u2h2(kh[kc * 2]);
                __half2 p1 = u2h2(kh[kc * 2 + 1]);
                aa[kc][0] = hmul2u(qa[kc][0], p0);
                aa[kc][1] = hmul2u(qa[kc][1], p0);
                aa[kc][2] = hmul2u(qa[kc][2], p1);
                aa[kc][3] = hmul2u(qa[kc][3], p1);
            }

            float sc[4][4];
#pragma unroll
            for (int nt = 0; nt < 4; ++nt)
#pragma unroll
                for (int r = 0; r < 4; ++r) sc[nt][r] = -M_LOG2;
#pragma unroll
            for (int kc = 0; kc < 4; ++kc)
#pragma unroll
                for (int nt = 0; nt < 4; ++nt)
                    mma16816(sc[nt], aa[kc][0], aa[kc][1], aa[kc][2], aa[kc][3],
                             bsf[kc][nt][0], bsf[kc][nt][1]);

            unsigned pa[2][4];
#pragma unroll
            for (int kc = 0; kc < 2; ++kc) {
                pa[kc][0] = p2exp(sc[2 * kc][0],     sc[2 * kc][1]);
                pa[kc][1] = p2exp(sc[2 * kc][2],     sc[2 * kc][3]);
                pa[kc][2] = p2exp(sc[2 * kc + 1][0], sc[2 * kc + 1][1]);
                pa[kc][3] = p2exp(sc[2 * kc + 1][2], sc[2 * kc + 1][3]);
            }

            mma16816(cl, pa[0][0], pa[0][1], pa[0][2], pa[0][3], BONES, BONES);
            mma16816(cl, pa[1][0], pa[1][1], pa[1][2], pa[1][3], BONES, BONES);

            const __half* v2p = v2t + (size_t)(kk * 8 + g) * 8;
            uint4 vraw = *(const uint4*)(v2p);
            const unsigned vhp[4] = {vraw.x, vraw.y, vraw.z, vraw.w};

#pragma unroll
            for (int nt = 0; nt < 8; ++nt) {
                __half2 pair = u2h2(vhp[nt >> 1]);
                __half2 vdd  = (nt & 1) ? __high2half2(pair) : __low2half2(pair);
#pragma unroll
                for (int kc = 0; kc < 2; ++kc) {
                    unsigned b0 = hmul2u(bvf[kc][nt][0], vdd);
                    unsigned b1 = hmul2u(bvf[kc][nt][1], vdd);
                    mma16816(pv[nt], pa[kc][0], pa[kc][1], pa[kc][2], pa[kc][3],
                             b0, b1);
                }
            }
        }
    }

    const int row0 = bh * SEQ + i0 + warp * 16 + g;
    const int row1 = row0 + 8;
    const int p0   = split * BHD * SEQ + row0;
    const int p1   = split * BHD * SEQ + row1;
    if (tg == 0) {
        pl[p0] = cl[0];
        pl[p1] = cl[2];
    }
#pragma unroll
    for (int nt = 0; nt < 8; ++nt) {
        int d = nt * 8 + 2 * tg;
        *(float2*)(pacc + (size_t)p0 * DH + d) = make_float2(pv[nt][0], pv[nt][1]);
        *(float2*)(pacc + (size_t)p1 * DH + d) = make_float2(pv[nt][2], pv[nt][3]);
    }
}

// ---------------------------------------------------------------------------
// Combine KSPLIT partials; write attn as fp16 hi/lo at [b,n,h*64+d].
// ---------------------------------------------------------------------------
__global__ __launch_bounds__(256) void combine_kernel(
    const float* __restrict__ pacc, const float* __restrict__ pl,
    __half* __restrict__ ahi, __half* __restrict__ alo)
{
    const int row = blockIdx.x * 4 + (threadIdx.x >> 6);
    const int d   = threadIdx.x & 63;

    float den = 0.f, num = 0.f;
#pragma unroll
    for (int s = 0; s < KSPLIT; ++s) {
        int idx = s * BHD * SEQ + row;
        den += pl[idx];
        num += pacc[(size_t)idx * DH + d];
    }
    float a = num / den;

    const int bh = row / SEQ, n = row % SEQ;
    const int b = bh >> 3, h = bh & 7;
    const int o = (b * SEQ + n) * DIMM + h * DH + d;
    __half hi = __float2half_rn(a);
    ahi[o] = hi;
    alo[o] = __float2half_rn(a - __half2float(hi));
}

// ---------------------------------------------------------------------------
extern "C" void kernel_launch(void* const* d_in, const int* in_sizes, int n_in,
                              void* d_out, int out_size)
{
    (void)in_sizes; (void)n_in; (void)out_size;
    const float* tokens = (const float*)d_in[0];
    const float* w_qkv  = (const float*)d_in[1];
    const float* w_out  = (const float*)d_in[2];
    const float* qw     = (const float*)d_in[3];
    const float* k1w    = (const float*)d_in[4];
    const float* k2w    = (const float*)d_in[5];
    const float* v1w    = (const float*)d_in[6];
    const float* v2w    = (const float*)d_in[7];
    float* out = (float*)d_out;

    float *qkv, *pacc, *plv;
    __half *hq, *hk1, *hk2, *hv1, *hv2;
    __half *th, *tl, *wqh, *wql, *woh, *wol, *ah, *al;
    cudaGetSymbolAddress((void**)&qkv,  g_qkv);
    cudaGetSymbolAddress((void**)&hq,   g_hq);
    cudaGetSymbolAddress((void**)&hk1,  g_hk1);
    cudaGetSymbolAddress((void**)&hk2,  g_hk2);
    cudaGetSymbolAddress((void**)&hv1,  g_hv1);
    cudaGetSymbolAddress((void**)&hv2,  g_hv2);
    cudaGetSymbolAddress((void**)&pacc, g_pacc);
    cudaGetSymbolAddress((void**)&plv,  g_pl);
    cudaGetSymbolAddress((void**)&th,   g_th);
    cudaGetSymbolAddress((void**)&tl,   g_tl);
    cudaGetSymbolAddress((void**)&wqh,  g_wqh);
    cudaGetSymbolAddress((void**)&wql,  g_wql);
    cudaGetSymbolAddress((void**)&woh,  g_woh);
    cudaGetSymbolAddress((void**)&wol,  g_wol);
    cudaGetSymbolAddress((void**)&ah,   g_ah);
    cudaGetSymbolAddress((void**)&al,   g_al);

    cudaFuncSetAttribute(attn_mma,
                         cudaFuncAttributeMaxDynamicSharedMemorySize,
                         ATTN_SMEM_BYTES);

    // 0) fused hi/lo splits of GEMM operands (one launch)
    split3_fp16<<<(N0Q + N1Q + N2Q + 255) / 256, 256>>>(
        tokens, th, tl, w_qkv, wqh, wql, w_out, woh, wol);
    // 1) qkv = tokens @ w_qkv^T : [384,2560]
    gemm_nt_tch<<<dim3(QKV_C / 64, ROWS / 64), 256>>>(th, tl, wqh, wql, qkv,
                                                      ROWS, QKV_C, DIMM);
    // 2) rmsnorm + split -> fp16
    rmsnorm_kernel<<<ROWS * HEADS / 8, 256>>>(qkv, qw, k1w, k2w, v1w, v2w,
                                              hq, hk1, hk2, hv1, hv2);
    // 3) tensor-core 2-simplicial attention, static-max split-K
    attn_mma<<<dim3(KSPLIT, SEQ / ITILE, BHD), NTHR, ATTN_SMEM_BYTES>>>(
        hq, hk1, hk2, hv1, hv2, pacc, plv);
    // 4) combine partials -> attn hi/lo
    combine_kernel<<<BHD * SEQ / 4, 256>>>(pacc, plv, ah, al);
    // 5) out = attn @ w_out^T : [384,512]
    gemm_nt_tch<<<dim3(DIMM / 64, ROWS / 64), 256>>>(ah, al, woh, wol, out,
                                                     ROWS, DIMM, DIMM);
}